// round 12
// baseline (speedup 1.0000x reference)
#include <cuda_runtime.h>
#include <cuda_bf16.h>
#include <math.h>
#include <stdint.h>

#define BATCH 4
#define SLEN 2048
#define DM 2048
#define NHEAD 16
#define HS 128
#define EPROJ (3 * DM)
#define KDIM 2048

// Scratch (no allocations allowed)
__device__ __nv_bfloat16 g_qhi[(size_t)BATCH * NHEAD * SLEN * HS];
__device__ __nv_bfloat16 g_qlo[(size_t)BATCH * NHEAD * SLEN * HS];
__device__ __nv_bfloat16 g_khi[(size_t)BATCH * NHEAD * SLEN * HS];
__device__ __nv_bfloat16 g_klo[(size_t)BATCH * NHEAD * SLEN * HS];
__device__ __nv_bfloat16 g_vhi[(size_t)BATCH * NHEAD * SLEN * HS];
__device__ __nv_bfloat16 g_vlo[(size_t)BATCH * NHEAD * SLEN * HS];
__device__ __nv_bfloat16 g_xhi[(size_t)BATCH * SLEN * DM];
__device__ __nv_bfloat16 g_xlo[(size_t)BATCH * SLEN * DM];
__device__ __nv_bfloat16 g_wphi[(size_t)EPROJ * DM];
__device__ __nv_bfloat16 g_wplo[(size_t)EPROJ * DM];
__device__ __nv_bfloat16 g_wfhi[(size_t)DM * DM];
__device__ __nv_bfloat16 g_wflo[(size_t)DM * DM];
__device__ __nv_bfloat16 g_athi[(size_t)BATCH * SLEN * DM];
__device__ __nv_bfloat16 g_atlo[(size_t)BATCH * SLEN * DM];

// ---------------------------------------------------------------------------
// helpers (non-arch-specific PTX only)
// ---------------------------------------------------------------------------
__device__ __forceinline__ uint32_t smem_u32(const void* p) {
    uint32_t a;
    asm("{ .reg .u64 t; cvta.to.shared.u64 t, %1; cvt.u32.u64 %0, t; }"
        : "=r"(a) : "l"(p));
    return a;
}

__device__ __forceinline__ void ldm_x4(uint32_t* r, uint32_t addr) {
    asm volatile("ldmatrix.sync.aligned.m8n8.x4.shared.b16 {%0,%1,%2,%3}, [%4];"
                 : "=r"(r[0]), "=r"(r[1]), "=r"(r[2]), "=r"(r[3]) : "r"(addr));
}

__device__ __forceinline__ void ldm_x4_t(uint32_t* r, uint32_t addr) {
    asm volatile("ldmatrix.sync.aligned.m8n8.x4.trans.shared.b16 {%0,%1,%2,%3}, [%4];"
                 : "=r"(r[0]), "=r"(r[1]), "=r"(r[2]), "=r"(r[3]) : "r"(addr));
}

__device__ __forceinline__ void mma_bf16(float* c, const uint32_t* a,
                                         const uint32_t* b) {
    asm volatile(
        "mma.sync.aligned.m16n8k16.row.col.f32.bf16.bf16.f32 "
        "{%0,%1,%2,%3}, {%4,%5,%6,%7}, {%8,%9}, {%0,%1,%2,%3};"
        : "+f"(c[0]), "+f"(c[1]), "+f"(c[2]), "+f"(c[3])
        : "r"(a[0]), "r"(a[1]), "r"(a[2]), "r"(a[3]), "r"(b[0]), "r"(b[1]));
}

#define CP_ASYNC16(dst, src) \
    asm volatile("cp.async.cg.shared.global [%0], [%1], 16;" \
                 :: "r"(dst), "l"(src))
#define CP_COMMIT() asm volatile("cp.async.commit_group;" ::: "memory")
#define CP_WAIT1() asm volatile("cp.async.wait_group 1;" ::: "memory")
#define CP_WAIT0() asm volatile("cp.async.wait_group 0;" ::: "memory")

__device__ __forceinline__ void split4(float4 v, uint2& hi, uint2& lo) {
    __nv_bfloat162 h01 = __floats2bfloat162_rn(v.x, v.y);
    __nv_bfloat162 h23 = __floats2bfloat162_rn(v.z, v.w);
    uint32_t u01 = *(uint32_t*)&h01, u23 = *(uint32_t*)&h23;
    float fx = __uint_as_float(u01 << 16);
    float fy = __uint_as_float(u01 & 0xffff0000u);
    float fz = __uint_as_float(u23 << 16);
    float fw = __uint_as_float(u23 & 0xffff0000u);
    __nv_bfloat162 l01 = __floats2bfloat162_rn(v.x - fx, v.y - fy);
    __nv_bfloat162 l23 = __floats2bfloat162_rn(v.z - fz, v.w - fw);
    hi = make_uint2(u01, u23);
    lo = make_uint2(*(uint32_t*)&l01, *(uint32_t*)&l23);
}

// fp32 -> bf16 hi/lo pre-split
__global__ __launch_bounds__(256) void split_kernel(
    const float4* __restrict__ src, uint2* __restrict__ hi,
    uint2* __restrict__ lo, int n4)
{
    int i = blockIdx.x * 256 + threadIdx.x;
    const int stride = gridDim.x * 256;
    for (; i < n4; i += stride) {
        uint2 h, l;
        split4(src[i], h, l);
        hi[i] = h;
        lo[i] = l;
    }
}

// ---------------------------------------------------------------------------
// bf16-split GEMM: C = A * W^T + bias (pre-split hi/lo operands).
// CTA 128x128, 4 warps (2Mx2N), warp tile 64x64, BK=32.
// Staging: synchronous grouped LDG.128 -> STS.128 (transient regs only),
// single 40KB buffer, 2 CTAs/SM (cross-CTA overlap hides staging latency).
// B fragments loaded in two nj-halves to bound register pressure.
// EPI==1: QKV epilogue (q scaled hi/lo; k/v fp32 d_out + hi/lo scratch).
// EPI==2: dense fp32 C.
// ---------------------------------------------------------------------------
#define PITCH 40
#define ARRB (128 * PITCH * 2)         // 10240 B per array

template <int EPI>
__global__ __launch_bounds__(128, 2) void gemm_bf_kernel(
    const __nv_bfloat16* __restrict__ Ahi, const __nv_bfloat16* __restrict__ Alo,
    const __nv_bfloat16* __restrict__ Whi, const __nv_bfloat16* __restrict__ Wlo,
    const float* __restrict__ bias, float* __restrict__ C,
    float* __restrict__ kout, float* __restrict__ vout)
{
    __shared__ __align__(16) char sm_bf[4 * ARRB];   // 40960 B

    const int K = KDIM;
    const int tid = threadIdx.x;
    const int wid = tid >> 5;      // 0..3
    const int lid = tid & 31;
    const int m0 = blockIdx.y * 128;
    const int n0 = blockIdx.x * 128;
    const int warpM = wid >> 1;    // 0..1
    const int warpN = wid & 1;     // 0..1

    const uint32_t sbase = smem_u32(sm_bf);

    // ldmatrix lane offsets
    const int q = lid >> 3, rr = lid & 7;
    const uint32_t aOff = sbase +
        (uint32_t)(((warpM * 64 + (q & 1) * 8 + rr) * PITCH + (q >> 1) * 8) * 2);
    const uint32_t bOff = sbase + 2 * ARRB +
        (uint32_t)(((warpN * 64 + (q >> 1) * 8 + rr) * PITCH + (q & 1) * 8) * 2);

    float acc[4][8][4];
#pragma unroll
    for (int i = 0; i < 4; i++)
#pragma unroll
        for (int j = 0; j < 8; j++)
#pragma unroll
            for (int r = 0; r < 4; r++) acc[i][j][r] = 0.f;

    // staging: thread -> one row (tid) of each of the 4 arrays, 32 bf16 (64B)
    const int srow = tid;
    const __nv_bfloat16* ps[4];
    ps[0] = Ahi + (size_t)(m0 + srow) * K;
    ps[1] = Alo + (size_t)(m0 + srow) * K;
    ps[2] = Whi + (size_t)(n0 + srow) * K;
    ps[3] = Wlo + (size_t)(n0 + srow) * K;
    const uint32_t sto = (uint32_t)(srow * PITCH * 2);

    for (int c = 0; c < 64; c++) {
        const int o = c * 32;
        __syncthreads();   // previous chunk's MMA done -> safe to overwrite
#pragma unroll
        for (int a = 0; a < 4; a++) {
            const uint4* p = (const uint4*)(ps[a] + o);
            uint4 t0 = p[0], t1 = p[1], t2 = p[2], t3 = p[3];
            char* d = sm_bf + a * ARRB + sto;
            *(uint4*)(d) = t0;
            *(uint4*)(d + 16) = t1;
            *(uint4*)(d + 32) = t2;
            *(uint4*)(d + 48) = t3;
        }
        __syncthreads();

#pragma unroll
        for (int ks = 0; ks < 2; ks++) {
            const uint32_t kb = (uint32_t)(ks * 32);
            uint32_t ah[4][4], al[4][4];
#pragma unroll
            for (int mi = 0; mi < 4; mi++) {
                const uint32_t off = (uint32_t)(mi * 16 * PITCH * 2) + kb;
                ldm_x4(ah[mi], aOff + off);
                ldm_x4(al[mi], aOff + ARRB + off);
            }
#pragma unroll
            for (int njh = 0; njh < 2; njh++) {
                uint32_t bh[2][4], bl[2][4];
#pragma unroll
                for (int pj = 0; pj < 2; pj++) {
                    const uint32_t off =
                        (uint32_t)((njh * 2 + pj) * 16 * PITCH * 2) + kb;
                    ldm_x4(bh[pj], bOff + off);
                    ldm_x4(bl[pj], bOff + ARRB + off);
                }
#pragma unroll
                for (int mi = 0; mi < 4; mi++)
#pragma unroll
                    for (int njl = 0; njl < 4; njl++) {
                        float* a4 = acc[mi][njh * 4 + njl];
                        const uint32_t* bhp = &bh[njl >> 1][(njl & 1) * 2];
                        const uint32_t* blp = &bl[njl >> 1][(njl & 1) * 2];
                        mma_bf16(a4, ah[mi], bhp);
                        mma_bf16(a4, al[mi], bhp);
                        mma_bf16(a4, ah[mi], blp);
                    }
            }
        }
    }

    // Epilogue
    const int t4 = lid >> 2;
    const int t2 = (lid & 3) << 1;
    if (EPI == 1) {
        const int seg = n0 >> 7;
        const int h = (int)((unsigned)seg / 3u);
        const int which = seg - h * 3;
        __nv_bfloat16 *hib, *lob;
        float* fpb = nullptr;
        if (which == 0)      { hib = g_qhi; lob = g_qlo; }
        else if (which == 1) { hib = g_khi; lob = g_klo; fpb = kout; }
        else                 { hib = g_vhi; lob = g_vlo; fpb = vout; }
        const float scl = (which == 0) ? 0.08838834764831845f : 1.0f;
#pragma unroll
        for (int mi = 0; mi < 4; mi++) {
            const int mrow = m0 + warpM * 64 + mi * 16 + t4;
            const int bb = mrow >> 11, ss = mrow & 2047;
            const size_t i0 = (((size_t)(bb * NHEAD + h)) * SLEN + ss) * HS;
            const size_t i1 = i0 + 8 * HS;
#pragma unroll
            for (int nj = 0; nj < 8; nj++) {
                const int col = warpN * 64 + nj * 8 + t2;
                const float2 bv = *(const float2*)(bias + n0 + col);
                float x0 = acc[mi][nj][0] + bv.x, x1 = acc[mi][nj][1] + bv.y;
                float y0 = acc[mi][nj][2] + bv.x, y1 = acc[mi][nj][3] + bv.y;
                if (which != 0) {
                    *(float2*)(fpb + i0 + col) = make_float2(x0, x1);
                    *(float2*)(fpb + i1 + col) = make_float2(y0, y1);
                }
                x0 *= scl; x1 *= scl; y0 *= scl; y1 *= scl;
                __nv_bfloat162 hx = __floats2bfloat162_rn(x0, x1);
                float2 hf = __bfloat1622float2(hx);
                __nv_bfloat162 lx = __floats2bfloat162_rn(x0 - hf.x, x1 - hf.y);
                __nv_bfloat162 hy = __floats2bfloat162_rn(y0, y1);
                float2 hg = __bfloat1622float2(hy);
                __nv_bfloat162 ly = __floats2bfloat162_rn(y0 - hg.x, y1 - hg.y);
                *(__nv_bfloat162*)(hib + i0 + col) = hx;
                *(__nv_bfloat162*)(lob + i0 + col) = lx;
                *(__nv_bfloat162*)(hib + i1 + col) = hy;
                *(__nv_bfloat162*)(lob + i1 + col) = ly;
            }
        }
    } else {
#pragma unroll
        for (int mi = 0; mi < 4; mi++) {
            const int mrow = m0 + warpM * 64 + mi * 16 + t4;
            float* d0 = C + (size_t)mrow * DM + n0;
            float* d1 = C + (size_t)(mrow + 8) * DM + n0;
#pragma unroll
            for (int nj = 0; nj < 8; nj++) {
                const int col = warpN * 64 + nj * 8 + t2;
                const float2 bv = *(const float2*)(bias + n0 + col);
                *(float2*)(d0 + col) =
                    make_float2(acc[mi][nj][0] + bv.x, acc[mi][nj][1] + bv.y);
                *(float2*)(d1 + col) =
                    make_float2(acc[mi][nj][2] + bv.x, acc[mi][nj][3] + bv.y);
            }
        }
    }
}

// ---------------------------------------------------------------------------
// Flash attention via mma.sync (FA2-style), causal, bf16 2-way split on both
// QK^T and PV. CTA = 128 q-rows x one (b*H+h); epilogue -> bf16 hi/lo.
// ---------------------------------------------------------------------------
#define QT 128
#define KT 64
#define Q_BYTES 32768
#define KV_ARR 16384
#define KV_BUF (4 * KV_ARR)
#define ATT_SMEM (2 * Q_BYTES + 2 * KV_BUF)  // 196608

__device__ __forceinline__ uint32_t swz(int row, int chunk) {
    return (uint32_t)(row * 256 + ((chunk ^ (row & 7)) << 4));
}

__global__ __launch_bounds__(256) void attn_mma_kernel()
{
    extern __shared__ __align__(16) char sm[];
    const uint32_t sb = smem_u32(sm);
    const int tid = threadIdx.x, wid = tid >> 5, lane = tid & 31;
    const int qb = blockIdx.x, bh = blockIdx.y;
    const int q0 = qb * QT;
    const int nkt = 2 * qb + 2;

    const size_t qoff = ((size_t)bh * SLEN + q0) * HS;
    const size_t kvoff = (size_t)bh * SLEN * HS;

    {
        const int half = tid >> 7;
        const __nv_bfloat16* src = (half ? g_qlo : g_qhi) + qoff;
        char* base = sm + half * Q_BYTES;
        int rc = tid & 127;
#pragma unroll
        for (int t = 0; t < 16; t++, rc += 128) {
            const int row = rc >> 4, c = rc & 15;
            uint4 v = *(const uint4*)(src + row * HS + c * 8);
            *(uint4*)(base + swz(row, c)) = v;
        }
    }

    const int karr = tid >> 6;
    const __nv_bfloat16* ksrc =
        ((karr == 0) ? g_khi : (karr == 1) ? g_klo : (karr == 2) ? g_vhi : g_vlo)
        + kvoff;
    const uint32_t kdstArr = sb + 2 * Q_BYTES + (uint32_t)(karr * KV_ARR);

    auto kv_issue = [&](int kt, int bf) {
        const __nv_bfloat16* s = ksrc + (size_t)kt * KT * HS;
        const uint32_t dbase = kdstArr + (uint32_t)(bf * KV_BUF);
        int rc = tid & 63;
#pragma unroll
        for (int t = 0; t < 16; t++, rc += 64) {
            const int row = rc >> 4, c = rc & 15;
            CP_ASYNC16(dbase + swz(row, c), s + row * HS + c * 8);
        }
    };

    kv_issue(0, 0);
    CP_COMMIT();

    float o[16][4];
#pragma unroll
    for (int t = 0; t < 16; t++)
#pragma unroll
        for (int r = 0; r < 4; r++) o[t][r] = 0.f;
    float m0r = -INFINITY, m1r = -INFINITY, l0r = 0.f, l1r = 0.f;

    const int aRow = wid * 16 + (lane & 7) + ((lane >> 3) & 1) * 8;
    const int aCh = lane >> 4;
    const int bRowK = (lane & 7) + (lane >> 4) * 8;
    const int bChK = (lane >> 3) & 1;
    const int vRow = (lane & 7) + ((lane >> 3) & 1) * 8;
    const int vCh = lane >> 4;

    for (int kt = 0; kt < nkt; kt++) {
        if (kt + 1 < nkt) {
            kv_issue(kt + 1, (kt + 1) & 1);
            CP_COMMIT();
            CP_WAIT1();
        } else {
            CP_WAIT0();
        }
        __syncthreads();

        const uint32_t kvb = sb + 2 * Q_BYTES + (uint32_t)((kt & 1) * KV_BUF);

        float s[8][4];
#pragma unroll
        for (int nj = 0; nj < 8; nj++)
#pragma unroll
            for (int r = 0; r < 4; r++) s[nj][r] = 0.f;

#pragma unroll
        for (int ks = 0; ks < 8; ks++) {
            uint32_t qh[4], ql[4];
            const uint32_t qa = sb + swz(aRow, 2 * ks + aCh);
            ldm_x4(qh, qa);
            ldm_x4(ql, qa + Q_BYTES);
#pragma unroll
            for (int njp = 0; njp < 4; njp++) {
                uint32_t kh[4], kl[4];
                const uint32_t ka = kvb + swz(njp * 16 + bRowK, 2 * ks + bChK);
                ldm_x4(kh, ka);
                ldm_x4(kl, ka + KV_ARR);
                mma_bf16(s[2 * njp], qh, kh);
                mma_bf16(s[2 * njp], ql, kh);
                mma_bf16(s[2 * njp], qh, kl);
                mma_bf16(s[2 * njp + 1], qh, kh + 2);
                mma_bf16(s[2 * njp + 1], ql, kh + 2);
                mma_bf16(s[2 * njp + 1], qh, kl + 2);
            }
        }

        const int r0g = q0 + wid * 16 + (lane >> 2);
        if (kt >= 2 * qb) {
            const int cb = kt * KT + (lane & 3) * 2;
#pragma unroll
            for (int nj = 0; nj < 8; nj++) {
                const int c0 = cb + nj * 8;
                if (c0 > r0g)         s[nj][0] = -INFINITY;
                if (c0 + 1 > r0g)     s[nj][1] = -INFINITY;
                if (c0 > r0g + 8)     s[nj][2] = -INFINITY;
                if (c0 + 1 > r0g + 8) s[nj][3] = -INFINITY;
            }
        }

        float tm0 = -INFINITY, tm1 = -INFINITY;
#pragma unroll
        for (int nj = 0; nj < 8; nj++) {
            tm0 = fmaxf(tm0, fmaxf(s[nj][0], s[nj][1]));
            tm1 = fmaxf(tm1, fmaxf(s[nj][2], s[nj][3]));
        }
        tm0 = fmaxf(tm0, __shfl_xor_sync(0xffffffffu, tm0, 1));
        tm0 = fmaxf(tm0, __shfl_xor_sync(0xffffffffu, tm0, 2));
        tm1 = fmaxf(tm1, __shfl_xor_sync(0xffffffffu, tm1, 1));
        tm1 = fmaxf(tm1, __shfl_xor_sync(0xffffffffu, tm1, 2));
        const float mn0 = fmaxf(m0r, tm0), mn1 = fmaxf(m1r, tm1);
        const float a0 = __expf(m0r - mn0), a1 = __expf(m1r - mn1);
        m0r = mn0; m1r = mn1;

        float ls0 = 0.f, ls1 = 0.f;
        uint32_t pah[4][4], pal[4][4];
#pragma unroll
        for (int nj = 0; nj < 8; nj++) {
            const float p0 = __expf(s[nj][0] - mn0);
            const float p1 = __expf(s[nj][1] - mn0);
            const float p2 = __expf(s[nj][2] - mn1);
            const float p3 = __expf(s[nj][3] - mn1);
            ls0 += p0 + p1;
            ls1 += p2 + p3;
            __nv_bfloat162 h01 = __floats2bfloat162_rn(p0, p1);
            float2 hf01 = __bfloat1622float2(h01);
            __nv_bfloat162 lo01 = __floats2bfloat162_rn(p0 - hf01.x, p1 - hf01.y);
            __nv_bfloat162 h23 = __floats2bfloat162_rn(p2, p3);
            float2 hf23 = __bfloat1622float2(h23);
            __nv_bfloat162 lo23 = __floats2bfloat162_rn(p2 - hf23.x, p3 - hf23.y);
            const int j = nj >> 1, e = (nj & 1) * 2;
            pah[j][e] = *(uint32_t*)&h01;
            pah[j][e + 1] = *(uint32_t*)&h23;
            pal[j][e] = *(uint32_t*)&lo01;
            pal[j][e + 1] = *(uint32_t*)&lo23;
        }
        ls0 += __shfl_xor_sync(0xffffffffu, ls0, 1);
        ls0 += __shfl_xor_sync(0xffffffffu, ls0, 2);
        ls1 += __shfl_xor_sync(0xffffffffu, ls1, 1);
        ls1 += __shfl_xor_sync(0xffffffffu, ls1, 2);
        l0r = l0r * a0 + ls0;
        l1r = l1r * a1 + ls1;

#pragma unroll
        for (int t = 0; t < 16; t++) {
            o[t][0] *= a0; o[t][1] *= a0;
            o[t][2] *= a1; o[t][3] *= a1;
        }

#pragma unroll
        for (int j = 0; j < 4; j++) {
#pragma unroll
            for (int nd = 0; nd < 8; nd++) {
                uint32_t vh[4], vl[4];
                const uint32_t va =
                    kvb + 2 * KV_ARR + swz(j * 16 + vRow, 2 * nd + vCh);
                ldm_x4_t(vh, va);
                ldm_x4_t(vl, va + KV_ARR);
                mma_bf16(o[2 * nd], pah[j], vh);
                mma_bf16(o[2 * nd], pal[j], vh);
                mma_bf16(o[2 * nd], pah[j], vl);
                mma_bf16(o[2 * nd + 1], pah[j], vh + 2);
                mma_bf16(o[2 * nd + 1], pal[j], vh + 2);
                mma_bf16(o[2 * nd + 1], pah[j], vl + 2);
            }
        }
        __syncthreads();
    }

    // write attn_o as bf16 hi/lo directly (consumed by FF GEMM)
    const float inv0 = 1.f / l0r, inv1 = 1.f / l1r;
    const int b = bh >> 4, h = bh & 15;
    const int r0g = q0 + wid * 16 + (lane >> 2);
    const size_t base0 =
        ((size_t)(b * SLEN + r0g)) * DM + h * HS + (lane & 3) * 2;
    const size_t base1 = base0 + (size_t)8 * DM;
#pragma unroll
    for (int t = 0; t < 16; t++) {
        float v0 = o[t][0] * inv0, v1 = o[t][1] * inv0;
        float w0 = o[t][2] * inv1, w1 = o[t][3] * inv1;
        __nv_bfloat162 h0 = __floats2bfloat162_rn(v0, v1);
        float2 f0 = __bfloat1622float2(h0);
        __nv_bfloat162 l0 = __floats2bfloat162_rn(v0 - f0.x, v1 - f0.y);
        __nv_bfloat162 h1 = __floats2bfloat162_rn(w0, w1);
        float2 f1 = __bfloat1622float2(h1);
        __nv_bfloat162 l1 = __floats2bfloat162_rn(w0 - f1.x, w1 - f1.y);
        *(__nv_bfloat162*)(g_athi + base0 + t * 8) = h0;
        *(__nv_bfloat162*)(g_atlo + base0 + t * 8) = l0;
        *(__nv_bfloat162*)(g_athi + base1 + t * 8) = h1;
        *(__nv_bfloat162*)(g_atlo + base1 + t * 8) = l1;
    }
}

// ---------------------------------------------------------------------------
extern "C" void kernel_launch(void* const* d_in, const int* in_sizes, int n_in,
                              void* d_out, int out_size)
{
    const float* x      = (const float*)d_in[0];
    const float* w_proj = (const float*)d_in[1];
    const float* b_proj = (const float*)d_in[2];
    const float* w_ff   = (const float*)d_in[3];
    const float* b_ff   = (const float*)d_in[4];

    float* out = (float*)d_out;
    float* ff   = out;
    float* kout = out + (size_t)BATCH * SLEN * DM;
    float* vout = kout + (size_t)BATCH * NHEAD * SLEN * HS;

    cudaFuncSetAttribute(attn_mma_kernel,
                         cudaFuncAttributeMaxDynamicSharedMemorySize, ATT_SMEM);

    __nv_bfloat16 *xhi, *xlo, *wphi, *wplo, *wfhi, *wflo, *athi, *atlo;
    cudaGetSymbolAddress((void**)&xhi, g_xhi);
    cudaGetSymbolAddress((void**)&xlo, g_xlo);
    cudaGetSymbolAddress((void**)&wphi, g_wphi);
    cudaGetSymbolAddress((void**)&wplo, g_wplo);
    cudaGetSymbolAddress((void**)&wfhi, g_wfhi);
    cudaGetSymbolAddress((void**)&wflo, g_wflo);
    cudaGetSymbolAddress((void**)&athi, g_athi);
    cudaGetSymbolAddress((void**)&atlo, g_atlo);

    // 0) pre-split fp32 -> bf16 hi/lo
    split_kernel<<<2048, 256>>>((const float4*)x, (uint2*)xhi, (uint2*)xlo,
                                (BATCH * SLEN * DM) / 4);
    split_kernel<<<2048, 256>>>((const float4*)w_proj, (uint2*)wphi, (uint2*)wplo,
                                (EPROJ * DM) / 4);
    split_kernel<<<1024, 256>>>((const float4*)w_ff, (uint2*)wfhi, (uint2*)wflo,
                                (DM * DM) / 4);

    // 1) QKV projection
    gemm_bf_kernel<1><<<dim3(EPROJ / 128, (BATCH * SLEN) / 128), 128>>>(
        xhi, xlo, wphi, wplo, b_proj, (float*)nullptr, kout, vout);

    // 2) Causal flash attention (mma.sync) -> g_athi/g_atlo
    attn_mma_kernel<<<dim3(SLEN / QT, BATCH * NHEAD), 256, ATT_SMEM>>>();

    // 3) FF projection
    gemm_bf_kernel<2><<<dim3(DM / 128, (BATCH * SLEN) / 128), 128>>>(
        athi, atlo, wfhi, wflo, b_ff, ff, (float*)nullptr, (float*)nullptr);
}

// round 13
// speedup vs baseline: 1.7515x; 1.7515x over previous
#include <cuda_runtime.h>
#include <cuda_bf16.h>
#include <math.h>
#include <stdint.h>

#define BATCH 4
#define SLEN 2048
#define DM 2048
#define NHEAD 16
#define HS 128
#define EPROJ (3 * DM)
#define KDIM 2048

// Scratch (no allocations allowed)
__device__ float g_attn[(size_t)BATCH * SLEN * DM];
__device__ __nv_bfloat16 g_qhi[(size_t)BATCH * NHEAD * SLEN * HS];
__device__ __nv_bfloat16 g_qlo[(size_t)BATCH * NHEAD * SLEN * HS];
__device__ __nv_bfloat16 g_khi[(size_t)BATCH * NHEAD * SLEN * HS];
__device__ __nv_bfloat16 g_klo[(size_t)BATCH * NHEAD * SLEN * HS];
__device__ __nv_bfloat16 g_vhi[(size_t)BATCH * NHEAD * SLEN * HS];
__device__ __nv_bfloat16 g_vlo[(size_t)BATCH * NHEAD * SLEN * HS];

// ---------------------------------------------------------------------------
// helpers (non-arch-specific PTX only)
// ---------------------------------------------------------------------------
__device__ __forceinline__ uint32_t smem_u32(const void* p) {
    uint32_t a;
    asm("{ .reg .u64 t; cvta.to.shared.u64 t, %1; cvt.u32.u64 %0, t; }"
        : "=r"(a) : "l"(p));
    return a;
}

__device__ __forceinline__ void ldm_x4(uint32_t* r, uint32_t addr) {
    asm volatile("ldmatrix.sync.aligned.m8n8.x4.shared.b16 {%0,%1,%2,%3}, [%4];"
                 : "=r"(r[0]), "=r"(r[1]), "=r"(r[2]), "=r"(r[3]) : "r"(addr));
}

__device__ __forceinline__ void ldm_x4_t(uint32_t* r, uint32_t addr) {
    asm volatile("ldmatrix.sync.aligned.m8n8.x4.trans.shared.b16 {%0,%1,%2,%3}, [%4];"
                 : "=r"(r[0]), "=r"(r[1]), "=r"(r[2]), "=r"(r[3]) : "r"(addr));
}

__device__ __forceinline__ void mma_bf16(float* c, const uint32_t* a,
                                         const uint32_t* b) {
    asm volatile(
        "mma.sync.aligned.m16n8k16.row.col.f32.bf16.bf16.f32 "
        "{%0,%1,%2,%3}, {%4,%5,%6,%7}, {%8,%9}, {%0,%1,%2,%3};"
        : "+f"(c[0]), "+f"(c[1]), "+f"(c[2]), "+f"(c[3])
        : "r"(a[0]), "r"(a[1]), "r"(a[2]), "r"(a[3]), "r"(b[0]), "r"(b[1]));
}

#define CP_ASYNC16(dst, src) \
    asm volatile("cp.async.cg.shared.global [%0], [%1], 16;" \
                 :: "r"(dst), "l"(src))
#define CP_COMMIT() asm volatile("cp.async.commit_group;" ::: "memory")
#define CP_WAIT1() asm volatile("cp.async.wait_group 1;" ::: "memory")
#define CP_WAIT0() asm volatile("cp.async.wait_group 0;" ::: "memory")

__device__ __forceinline__ void split4(float4 v, uint2& hi, uint2& lo) {
    __nv_bfloat162 h01 = __floats2bfloat162_rn(v.x, v.y);
    __nv_bfloat162 h23 = __floats2bfloat162_rn(v.z, v.w);
    uint32_t u01 = *(uint32_t*)&h01, u23 = *(uint32_t*)&h23;
    float fx = __uint_as_float(u01 << 16);
    float fy = __uint_as_float(u01 & 0xffff0000u);
    float fz = __uint_as_float(u23 << 16);
    float fw = __uint_as_float(u23 & 0xffff0000u);
    __nv_bfloat162 l01 = __floats2bfloat162_rn(v.x - fx, v.y - fy);
    __nv_bfloat162 l23 = __floats2bfloat162_rn(v.z - fz, v.w - fw);
    hi = make_uint2(u01, u23);
    lo = make_uint2(*(uint32_t*)&l01, *(uint32_t*)&l23);
}

// ---------------------------------------------------------------------------
// mma.sync bf16-split GEMM (R5 config + double-buffered smem, 1 sync/chunk):
// C = A * W^T + bias. CTA 128x128, 8 warps (2Mx4N), warp 64x32, BK=32,
// in-kernel fp32->hi/lo split staging with register prefetch.
// EPI==1: QKV epilogue -> q(scaled) hi/lo scratch, k/v fp32 d_out + hi/lo.
// EPI==2: dense C (A = g_attn).
// ---------------------------------------------------------------------------
#define PITCH 40
#define TILE_E (128 * PITCH)
#define BUF_E (4 * TILE_E)             // elements per buffer (4 arrays)
#define GEMM_SMEM (2 * BUF_E * 2)      // 81920 bytes
#define AHI 0
#define ALO TILE_E
#define WHI (2 * TILE_E)
#define WLO (3 * TILE_E)

template <int EPI>
__global__ __launch_bounds__(256) void gemm_mma_kernel(
    const float* __restrict__ Ain, const float* __restrict__ W,
    const float* __restrict__ bias, float* __restrict__ C,
    float* __restrict__ kout, float* __restrict__ vout)
{
    extern __shared__ __align__(16) char sm_bf[];

    const float* A = (EPI == 2) ? (const float*)g_attn : Ain;
    const int K = KDIM;
    const int tid = threadIdx.x;
    const int wid = tid >> 5;
    const int lid = tid & 31;
    const int m0 = blockIdx.y * 128;
    const int n0 = blockIdx.x * 128;
    const int warpM = wid >> 2;
    const int warpN = wid & 3;

    const uint32_t sbase = smem_u32(sm_bf);

    const int q = lid >> 3, rr = lid & 7;
    const uint32_t aAddr = sbase +
        (uint32_t)(((warpM * 64 + (q & 1) * 8 + rr) * PITCH + (q >> 1) * 8) * 2);
    const uint32_t bAddr = sbase +
        (uint32_t)(((warpN * 32 + (q >> 1) * 8 + rr) * PITCH + (q & 1) * 8) * 2);

    float acc[4][4][4];
#pragma unroll
    for (int i = 0; i < 4; i++)
#pragma unroll
        for (int j = 0; j < 4; j++)
#pragma unroll
            for (int r = 0; r < 4; r++) acc[i][j][r] = 0.f;

    const int srow = tid >> 1;
    const int scol = (tid & 1) << 4;
    const float* Aptr = A + (size_t)(m0 + srow) * K + scol;
    const float* Wptr = W + (size_t)(n0 + srow) * K + scol;
    const uint32_t sto = (uint32_t)(srow * PITCH + scol);

    float4 va[4], vw[4];
#pragma unroll
    for (int i = 0; i < 4; i++) {
        va[i] = *(const float4*)(Aptr + i * 4);
        vw[i] = *(const float4*)(Wptr + i * 4);
    }

    for (int c = 0; c < 64; c++) {
        const uint32_t bufB = (uint32_t)((c & 1) * (BUF_E * 2));  // byte offset
        char* sb0 = sm_bf + bufB;
        // store chunk c into buffer c&1 (other buffer may still be read by
        // laggard warps' MMA of chunk c-1 — different buffer, safe)
#pragma unroll
        for (int i = 0; i < 4; i++) {
            uint2 hi, lo;
            split4(va[i], hi, lo);
            *(uint2*)(sb0 + (size_t)(AHI + sto + i * 4) * 2) = hi;
            *(uint2*)(sb0 + (size_t)(ALO + sto + i * 4) * 2) = lo;
            split4(vw[i], hi, lo);
            *(uint2*)(sb0 + (size_t)(WHI + sto + i * 4) * 2) = hi;
            *(uint2*)(sb0 + (size_t)(WLO + sto + i * 4) * 2) = lo;
        }
        if (c < 63) {
            const float* ap = Aptr + (c + 1) * 32;
            const float* wp = Wptr + (c + 1) * 32;
#pragma unroll
            for (int i = 0; i < 4; i++) {
                va[i] = *(const float4*)(ap + i * 4);
                vw[i] = *(const float4*)(wp + i * 4);
            }
        }
        __syncthreads();   // stores of chunk c visible; mma(c-1) done everywhere

#pragma unroll
        for (int ks = 0; ks < 2; ks++) {
            const uint32_t kb = (uint32_t)(ks * 32);
            uint32_t ah[4][4], al[4][4], bh[2][4], bl[2][4];
#pragma unroll
            for (int mi = 0; mi < 4; mi++) {
                const uint32_t off = (uint32_t)(mi * 16 * PITCH * 2) + kb + bufB;
                ldm_x4(ah[mi], aAddr + off);
                ldm_x4(al[mi], aAddr + ALO * 2 + off);
            }
#pragma unroll
            for (int pj = 0; pj < 2; pj++) {
                const uint32_t off = (uint32_t)(pj * 16 * PITCH * 2) + kb + bufB;
                ldm_x4(bh[pj], bAddr + WHI * 2 + off);
                ldm_x4(bl[pj], bAddr + WLO * 2 + off);
            }
#pragma unroll
            for (int mi = 0; mi < 4; mi++)
#pragma unroll
                for (int nj = 0; nj < 4; nj++) {
                    const uint32_t* bhp = &bh[nj >> 1][(nj & 1) * 2];
                    const uint32_t* blp = &bl[nj >> 1][(nj & 1) * 2];
                    mma_bf16(acc[mi][nj], ah[mi], bhp);
                    mma_bf16(acc[mi][nj], al[mi], bhp);
                    mma_bf16(acc[mi][nj], ah[mi], blp);
                }
        }
    }

    // Epilogue
    const int t4 = lid >> 2;
    const int t2 = (lid & 3) << 1;
    if (EPI == 1) {
        const int seg = n0 >> 7;
        const int h = (int)((unsigned)seg / 3u);
        const int which = seg - h * 3;
        __nv_bfloat16 *hib, *lob;
        float* fpb = nullptr;
        if (which == 0)      { hib = g_qhi; lob = g_qlo; }
        else if (which == 1) { hib = g_khi; lob = g_klo; fpb = kout; }
        else                 { hib = g_vhi; lob = g_vlo; fpb = vout; }
        const float scl = (which == 0) ? 0.08838834764831845f : 1.0f;
#pragma unroll
        for (int mi = 0; mi < 4; mi++) {
            const int mrow = m0 + warpM * 64 + mi * 16 + t4;
            const int bb = mrow >> 11, ss = mrow & 2047;
            const size_t i0 = (((size_t)(bb * NHEAD + h)) * SLEN + ss) * HS;
            const size_t i1 = i0 + 8 * HS;
#pragma unroll
            for (int nj = 0; nj < 4; nj++) {
                const int col = warpN * 32 + nj * 8 + t2;
                const float2 bv = *(const float2*)(bias + n0 + col);
                float x0 = acc[mi][nj][0] + bv.x, x1 = acc[mi][nj][1] + bv.y;
                float y0 = acc[mi][nj][2] + bv.x, y1 = acc[mi][nj][3] + bv.y;
                if (which != 0) {
                    *(float2*)(fpb + i0 + col) = make_float2(x0, x1);
                    *(float2*)(fpb + i1 + col) = make_float2(y0, y1);
                }
                x0 *= scl; x1 *= scl; y0 *= scl; y1 *= scl;
                __nv_bfloat162 hx = __floats2bfloat162_rn(x0, x1);
                float2 hf = __bfloat1622float2(hx);
                __nv_bfloat162 lx = __floats2bfloat162_rn(x0 - hf.x, x1 - hf.y);
                __nv_bfloat162 hy = __floats2bfloat162_rn(y0, y1);
                float2 hg = __bfloat1622float2(hy);
                __nv_bfloat162 ly = __floats2bfloat162_rn(y0 - hg.x, y1 - hg.y);
                *(__nv_bfloat162*)(hib + i0 + col) = hx;
                *(__nv_bfloat162*)(lob + i0 + col) = lx;
                *(__nv_bfloat162*)(hib + i1 + col) = hy;
                *(__nv_bfloat162*)(lob + i1 + col) = ly;
            }
        }
    } else {
#pragma unroll
        for (int mi = 0; mi < 4; mi++) {
            const int mrow = m0 + warpM * 64 + mi * 16 + t4;
            float* d0 = C + (size_t)mrow * DM + n0;
            float* d1 = C + (size_t)(mrow + 8) * DM + n0;
#pragma unroll
            for (int nj = 0; nj < 4; nj++) {
                const int col = warpN * 32 + nj * 8 + t2;
                const float2 bv = *(const float2*)(bias + n0 + col);
                *(float2*)(d0 + col) =
                    make_float2(acc[mi][nj][0] + bv.x, acc[mi][nj][1] + bv.y);
                *(float2*)(d1 + col) =
                    make_float2(acc[mi][nj][2] + bv.x, acc[mi][nj][3] + bv.y);
            }
        }
    }
}

// ---------------------------------------------------------------------------
// Flash attention via mma.sync (FA2-style), causal, bf16 2-way split on both
// QK^T and PV. CTA = 128 q-rows x one (b*H+h); KV tiles of 64, cp.async
// double-buffered. Writes fp32 attn_o to g_attn (exact R5 form).
// ---------------------------------------------------------------------------
#define QT 128
#define KT 64
#define Q_BYTES 32768
#define KV_ARR 16384
#define KV_BUF (4 * KV_ARR)
#define ATT_SMEM (2 * Q_BYTES + 2 * KV_BUF)  // 196608

__device__ __forceinline__ uint32_t swz(int row, int chunk) {
    return (uint32_t)(row * 256 + ((chunk ^ (row & 7)) << 4));
}

__global__ __launch_bounds__(256) void attn_mma_kernel()
{
    extern __shared__ __align__(16) char sm[];
    const uint32_t sb = smem_u32(sm);
    const int tid = threadIdx.x, wid = tid >> 5, lane = tid & 31;
    const int qb = blockIdx.x, bh = blockIdx.y;
    const int q0 = qb * QT;
    const int nkt = 2 * qb + 2;

    const size_t qoff = ((size_t)bh * SLEN + q0) * HS;
    const size_t kvoff = (size_t)bh * SLEN * HS;

    {
        const int half = tid >> 7;
        const __nv_bfloat16* src = (half ? g_qlo : g_qhi) + qoff;
        char* base = sm + half * Q_BYTES;
        int rc = tid & 127;
#pragma unroll
        for (int t = 0; t < 16; t++, rc += 128) {
            const int row = rc >> 4, c = rc & 15;
            uint4 v = *(const uint4*)(src + row * HS + c * 8);
            *(uint4*)(base + swz(row, c)) = v;
        }
    }

    const int karr = tid >> 6;
    const __nv_bfloat16* ksrc =
        ((karr == 0) ? g_khi : (karr == 1) ? g_klo : (karr == 2) ? g_vhi : g_vlo)
        + kvoff;
    const uint32_t kdstArr = sb + 2 * Q_BYTES + (uint32_t)(karr * KV_ARR);

    auto kv_issue = [&](int kt, int bf) {
        const __nv_bfloat16* s = ksrc + (size_t)kt * KT * HS;
        const uint32_t dbase = kdstArr + (uint32_t)(bf * KV_BUF);
        int rc = tid & 63;
#pragma unroll
        for (int t = 0; t < 16; t++, rc += 64) {
            const int row = rc >> 4, c = rc & 15;
            CP_ASYNC16(dbase + swz(row, c), s + row * HS + c * 8);
        }
    };

    kv_issue(0, 0);
    CP_COMMIT();

    float o[16][4];
#pragma unroll
    for (int t = 0; t < 16; t++)
#pragma unroll
        for (int r = 0; r < 4; r++) o[t][r] = 0.f;
    float m0r = -INFINITY, m1r = -INFINITY, l0r = 0.f, l1r = 0.f;

    const int aRow = wid * 16 + (lane & 7) + ((lane >> 3) & 1) * 8;
    const int aCh = lane >> 4;
    const int bRowK = (lane & 7) + (lane >> 4) * 8;
    const int bChK = (lane >> 3) & 1;
    const int vRow = (lane & 7) + ((lane >> 3) & 1) * 8;
    const int vCh = lane >> 4;

    for (int kt = 0; kt < nkt; kt++) {
        if (kt + 1 < nkt) {
            kv_issue(kt + 1, (kt + 1) & 1);
            CP_COMMIT();
            CP_WAIT1();
        } else {
            CP_WAIT0();
        }
        __syncthreads();

        const uint32_t kvb = sb + 2 * Q_BYTES + (uint32_t)((kt & 1) * KV_BUF);

        float s[8][4];
#pragma unroll
        for (int nj = 0; nj < 8; nj++)
#pragma unroll
            for (int r = 0; r < 4; r++) s[nj][r] = 0.f;

#pragma unroll
        for (int ks = 0; ks < 8; ks++) {
            uint32_t qh[4], ql[4];
            const uint32_t qa = sb + swz(aRow, 2 * ks + aCh);
            ldm_x4(qh, qa);
            ldm_x4(ql, qa + Q_BYTES);
#pragma unroll
            for (int njp = 0; njp < 4; njp++) {
                uint32_t kh[4], kl[4];
                const uint32_t ka = kvb + swz(njp * 16 + bRowK, 2 * ks + bChK);
                ldm_x4(kh, ka);
                ldm_x4(kl, ka + KV_ARR);
                mma_bf16(s[2 * njp], qh, kh);
                mma_bf16(s[2 * njp], ql, kh);
                mma_bf16(s[2 * njp], qh, kl);
                mma_bf16(s[2 * njp + 1], qh, kh + 2);
                mma_bf16(s[2 * njp + 1], ql, kh + 2);
                mma_bf16(s[2 * njp + 1], qh, kl + 2);
            }
        }

        const int r0g = q0 + wid * 16 + (lane >> 2);
        if (kt >= 2 * qb) {
            const int cb = kt * KT + (lane & 3) * 2;
#pragma unroll
            for (int nj = 0; nj < 8; nj++) {
                const int c0 = cb + nj * 8;
                if (c0 > r0g)         s[nj][0] = -INFINITY;
                if (c0 + 1 > r0g)     s[nj][1] = -INFINITY;
                if (c0 > r0g + 8)     s[nj][2] = -INFINITY;
                if (c0 + 1 > r0g + 8) s[nj][3] = -INFINITY;
            }
        }

        float tm0 = -INFINITY, tm1 = -INFINITY;
#pragma unroll
        for (int nj = 0; nj < 8; nj++) {
            tm0 = fmaxf(tm0, fmaxf(s[nj][0], s[nj][1]));
            tm1 = fmaxf(tm1, fmaxf(s[nj][2], s[nj][3]));
        }
        tm0 = fmaxf(tm0, __shfl_xor_sync(0xffffffffu, tm0, 1));
        tm0 = fmaxf(tm0, __shfl_xor_sync(0xffffffffu, tm0, 2));
        tm1 = fmaxf(tm1, __shfl_xor_sync(0xffffffffu, tm1, 1));
        tm1 = fmaxf(tm1, __shfl_xor_sync(0xffffffffu, tm1, 2));
        const float mn0 = fmaxf(m0r, tm0), mn1 = fmaxf(m1r, tm1);
        const float a0 = __expf(m0r - mn0), a1 = __expf(m1r - mn1);
        m0r = mn0; m1r = mn1;

        float ls0 = 0.f, ls1 = 0.f;
        uint32_t pah[4][4], pal[4][4];
#pragma unroll
        for (int nj = 0; nj < 8; nj++) {
            const float p0 = __expf(s[nj][0] - mn0);
            const float p1 = __expf(s[nj][1] - mn0);
            const float p2 = __expf(s[nj][2] - mn1);
            const float p3 = __expf(s[nj][3] - mn1);
            ls0 += p0 + p1;
            ls1 += p2 + p3;
            __nv_bfloat162 h01 = __floats2bfloat162_rn(p0, p1);
            float2 hf01 = __bfloat1622float2(h01);
            __nv_bfloat162 lo01 = __floats2bfloat162_rn(p0 - hf01.x, p1 - hf01.y);
            __nv_bfloat162 h23 = __floats2bfloat162_rn(p2, p3);
            float2 hf23 = __bfloat1622float2(h23);
            __nv_bfloat162 lo23 = __floats2bfloat162_rn(p2 - hf23.x, p3 - hf23.y);
            const int j = nj >> 1, e = (nj & 1) * 2;
            pah[j][e] = *(uint32_t*)&h01;
            pah[j][e + 1] = *(uint32_t*)&h23;
            pal[j][e] = *(uint32_t*)&lo01;
            pal[j][e + 1] = *(uint32_t*)&lo23;
        }
        ls0 += __shfl_xor_sync(0xffffffffu, ls0, 1);
        ls0 += __shfl_xor_sync(0xffffffffu, ls0, 2);
        ls1 += __shfl_xor_sync(0xffffffffu, ls1, 1);
        ls1 += __shfl_xor_sync(0xffffffffu, ls1, 2);
        l0r = l0r * a0 + ls0;
        l1r = l1r * a1 + ls1;

#pragma unroll
        for (int t = 0; t < 16; t++) {
            o[t][0] *= a0; o[t][1] *= a0;
            o[t][2] *= a1; o[t][3] *= a1;
        }

#pragma unroll
        for (int j = 0; j < 4; j++) {
#pragma unroll
            for (int nd = 0; nd < 8; nd++) {
                uint32_t vh[4], vl[4];
                const uint32_t va =
                    kvb + 2 * KV_ARR + swz(j * 16 + vRow, 2 * nd + vCh);
                ldm_x4_t(vh, va);
                ldm_x4_t(vl, va + KV_ARR);
                mma_bf16(o[2 * nd], pah[j], vh);
                mma_bf16(o[2 * nd], pal[j], vh);
                mma_bf16(o[2 * nd], pah[j], vl);
                mma_bf16(o[2 * nd + 1], pah[j], vh + 2);
                mma_bf16(o[2 * nd + 1], pal[j], vh + 2);
                mma_bf16(o[2 * nd + 1], pah[j], vl + 2);
            }
        }
        __syncthreads();
    }

    // write attn_o (normalized, fp32) to g_attn [B,S,D]
    const float inv0 = 1.f / l0r, inv1 = 1.f / l1r;
    const int b = bh >> 4, h = bh & 15;
    const int r0g = q0 + wid * 16 + (lane >> 2);
    float* d0 = g_attn + ((size_t)(b * SLEN + r0g)) * DM + h * HS + (lane & 3) * 2;
    float* d1 = d0 + (size_t)8 * DM;
#pragma unroll
    for (int t = 0; t < 16; t++) {
        *(float2*)(d0 + t * 8) = make_float2(o[t][0] * inv0, o[t][1] * inv0);
        *(float2*)(d1 + t * 8) = make_float2(o[t][2] * inv1, o[t][3] * inv1);
    }
}

// ---------------------------------------------------------------------------
extern "C" void kernel_launch(void* const* d_in, const int* in_sizes, int n_in,
                              void* d_out, int out_size)
{
    const float* x      = (const float*)d_in[0];
    const float* w_proj = (const float*)d_in[1];
    const float* b_proj = (const float*)d_in[2];
    const float* w_ff   = (const float*)d_in[3];
    const float* b_ff   = (const float*)d_in[4];

    float* out = (float*)d_out;
    float* ff   = out;
    float* kout = out + (size_t)BATCH * SLEN * DM;
    float* vout = kout + (size_t)BATCH * NHEAD * SLEN * HS;

    cudaFuncSetAttribute(attn_mma_kernel,
                         cudaFuncAttributeMaxDynamicSharedMemorySize, ATT_SMEM);
    cudaFuncSetAttribute(gemm_mma_kernel<1>,
                         cudaFuncAttributeMaxDynamicSharedMemorySize, GEMM_SMEM);
    cudaFuncSetAttribute(gemm_mma_kernel<2>,
                         cudaFuncAttributeMaxDynamicSharedMemorySize, GEMM_SMEM);

    // 1) QKV projection: q(scaled) hi/lo -> scratch, k/v fp32 -> d_out + hi/lo
    gemm_mma_kernel<1><<<dim3(EPROJ / 128, (BATCH * SLEN) / 128), 256, GEMM_SMEM>>>(
        x, w_proj, b_proj, (float*)nullptr, kout, vout);

    // 2) Causal flash attention (mma.sync) -> g_attn
    attn_mma_kernel<<<dim3(SLEN / QT, BATCH * NHEAD), 256, ATT_SMEM>>>();

    // 3) FF projection -> ff output
    gemm_mma_kernel<2><<<dim3(DM / 128, (BATCH * SLEN) / 128), 256, GEMM_SMEM>>>(
        (const float*)nullptr, w_ff, b_ff, ff, (float*)nullptr, (float*)nullptr);
}

// round 14
// speedup vs baseline: 1.8599x; 1.0619x over previous
#include <cuda_runtime.h>
#include <cuda_bf16.h>
#include <math.h>
#include <stdint.h>

#define BATCH 4
#define SLEN 2048
#define DM 2048
#define NHEAD 16
#define HS 128
#define EPROJ (3 * DM)
#define KDIM 2048

// Scratch (no allocations allowed)
__device__ float g_attn[(size_t)BATCH * SLEN * DM];
__device__ __nv_bfloat16 g_qhi[(size_t)BATCH * NHEAD * SLEN * HS];
__device__ __nv_bfloat16 g_qlo[(size_t)BATCH * NHEAD * SLEN * HS];
__device__ __nv_bfloat16 g_khi[(size_t)BATCH * NHEAD * SLEN * HS];
__device__ __nv_bfloat16 g_klo[(size_t)BATCH * NHEAD * SLEN * HS];
__device__ __nv_bfloat16 g_vhi[(size_t)BATCH * NHEAD * SLEN * HS];
__device__ __nv_bfloat16 g_vlo[(size_t)BATCH * NHEAD * SLEN * HS];

// ---------------------------------------------------------------------------
// helpers (non-arch-specific PTX only)
// ---------------------------------------------------------------------------
__device__ __forceinline__ uint32_t smem_u32(const void* p) {
    uint32_t a;
    asm("{ .reg .u64 t; cvta.to.shared.u64 t, %1; cvt.u32.u64 %0, t; }"
        : "=r"(a) : "l"(p));
    return a;
}

__device__ __forceinline__ void ldm_x4(uint32_t* r, uint32_t addr) {
    asm volatile("ldmatrix.sync.aligned.m8n8.x4.shared.b16 {%0,%1,%2,%3}, [%4];"
                 : "=r"(r[0]), "=r"(r[1]), "=r"(r[2]), "=r"(r[3]) : "r"(addr));
}

__device__ __forceinline__ void ldm_x4_t(uint32_t* r, uint32_t addr) {
    asm volatile("ldmatrix.sync.aligned.m8n8.x4.trans.shared.b16 {%0,%1,%2,%3}, [%4];"
                 : "=r"(r[0]), "=r"(r[1]), "=r"(r[2]), "=r"(r[3]) : "r"(addr));
}

__device__ __forceinline__ void mma_bf16(float* c, const uint32_t* a,
                                         const uint32_t* b) {
    asm volatile(
        "mma.sync.aligned.m16n8k16.row.col.f32.bf16.bf16.f32 "
        "{%0,%1,%2,%3}, {%4,%5,%6,%7}, {%8,%9}, {%0,%1,%2,%3};"
        : "+f"(c[0]), "+f"(c[1]), "+f"(c[2]), "+f"(c[3])
        : "r"(a[0]), "r"(a[1]), "r"(a[2]), "r"(a[3]), "r"(b[0]), "r"(b[1]));
}

#define CP_ASYNC16(dst, src) \
    asm volatile("cp.async.cg.shared.global [%0], [%1], 16;" \
                 :: "r"(dst), "l"(src))
#define CP_COMMIT() asm volatile("cp.async.commit_group;" ::: "memory")
#define CP_WAIT1() asm volatile("cp.async.wait_group 1;" ::: "memory")
#define CP_WAIT0() asm volatile("cp.async.wait_group 0;" ::: "memory")

__device__ __forceinline__ void split4(float4 v, uint2& hi, uint2& lo) {
    __nv_bfloat162 h01 = __floats2bfloat162_rn(v.x, v.y);
    __nv_bfloat162 h23 = __floats2bfloat162_rn(v.z, v.w);
    uint32_t u01 = *(uint32_t*)&h01, u23 = *(uint32_t*)&h23;
    float fx = __uint_as_float(u01 << 16);
    float fy = __uint_as_float(u01 & 0xffff0000u);
    float fz = __uint_as_float(u23 << 16);
    float fw = __uint_as_float(u23 & 0xffff0000u);
    __nv_bfloat162 l01 = __floats2bfloat162_rn(v.x - fx, v.y - fy);
    __nv_bfloat162 l23 = __floats2bfloat162_rn(v.z - fz, v.w - fw);
    hi = make_uint2(u01, u23);
    lo = make_uint2(*(uint32_t*)&l01, *(uint32_t*)&l23);
}

// ---------------------------------------------------------------------------
// mma.sync bf16-split GEMM: C = A * W^T + bias.
// CTA 256x128, 8 warps (4Mx2N), warp tile 64x64, BK=32.
// R5-style staging (fp32 LDG -> in-kernel split -> STS, register prefetch:
// each thread owns A rows r & r+128 and W row r, one 16-col half), R13-style
// double-buffered smem, one sync per chunk.
// EPI==1: QKV epilogue -> q(scaled) hi/lo scratch, k/v fp32 d_out + hi/lo.
// EPI==2: dense C (A = g_attn).
// ---------------------------------------------------------------------------
#define PITCH 40
#define A_ARR (256 * PITCH * 2)        // 20480 B (Ahi / Alo each)
#define W_ARR (128 * PITCH * 2)        // 10240 B (Whi / Wlo each)
#define BUF_B (2 * A_ARR + 2 * W_ARR)  // 61440 B per buffer
#define GEMM_SMEM (2 * BUF_B)          // 122880 B

template <int EPI>
__global__ __launch_bounds__(256) void gemm_mma_kernel(
    const float* __restrict__ Ain, const float* __restrict__ W,
    const float* __restrict__ bias, float* __restrict__ C,
    float* __restrict__ kout, float* __restrict__ vout)
{
    extern __shared__ __align__(16) char sm_bf[];

    const float* A = (EPI == 2) ? (const float*)g_attn : Ain;
    const int K = KDIM;
    const int tid = threadIdx.x;
    const int wid = tid >> 5;
    const int lid = tid & 31;
    const int m0 = blockIdx.y * 256;
    const int n0 = blockIdx.x * 128;
    const int warpM = wid >> 1;    // 0..3
    const int warpN = wid & 1;     // 0..1

    const uint32_t sbase = smem_u32(sm_bf);

    // ldmatrix lane offsets (relative to buffer base)
    const int q = lid >> 3, rr = lid & 7;
    const uint32_t aOff =
        (uint32_t)(((warpM * 64 + (q & 1) * 8 + rr) * PITCH + (q >> 1) * 8) * 2);
    const uint32_t bOff =
        (uint32_t)(((warpN * 64 + (q >> 1) * 8 + rr) * PITCH + (q & 1) * 8) * 2);

    float acc[4][8][4];
#pragma unroll
    for (int i = 0; i < 4; i++)
#pragma unroll
        for (int j = 0; j < 8; j++)
#pragma unroll
            for (int r = 0; r < 4; r++) acc[i][j][r] = 0.f;

    // staging: r = tid>>1 (0..127), half h = tid&1 (cols h*16 .. h*16+15)
    const int r = tid >> 1;
    const int h = tid & 1;
    const float* pA0 = A + (size_t)(m0 + r) * K + h * 16;
    const float* pA1 = A + (size_t)(m0 + 128 + r) * K + h * 16;
    const float* pW  = W + (size_t)(n0 + r) * K + h * 16;
    const uint32_t stoA0 = (uint32_t)(r * PITCH + h * 16);
    const uint32_t stoA1 = (uint32_t)((128 + r) * PITCH + h * 16);
    const uint32_t stoW  = stoA0;

    float4 va0[4], va1[4], vw[4];
#pragma unroll
    for (int i = 0; i < 4; i++) {
        va0[i] = *(const float4*)(pA0 + i * 4);
        va1[i] = *(const float4*)(pA1 + i * 4);
        vw[i]  = *(const float4*)(pW  + i * 4);
    }

    for (int c = 0; c < 64; c++) {
        const uint32_t bufB = (uint32_t)((c & 1) * BUF_B);
        char* sb0 = sm_bf + bufB;
#pragma unroll
        for (int i = 0; i < 4; i++) {
            uint2 hi, lo;
            split4(va0[i], hi, lo);
            *(uint2*)(sb0 + (size_t)(stoA0 + i * 4) * 2) = hi;
            *(uint2*)(sb0 + A_ARR + (size_t)(stoA0 + i * 4) * 2) = lo;
            split4(va1[i], hi, lo);
            *(uint2*)(sb0 + (size_t)(stoA1 + i * 4) * 2) = hi;
            *(uint2*)(sb0 + A_ARR + (size_t)(stoA1 + i * 4) * 2) = lo;
            split4(vw[i], hi, lo);
            *(uint2*)(sb0 + 2 * A_ARR + (size_t)(stoW + i * 4) * 2) = hi;
            *(uint2*)(sb0 + 2 * A_ARR + W_ARR + (size_t)(stoW + i * 4) * 2) = lo;
        }
        if (c < 63) {
            const int o = (c + 1) * 32;
#pragma unroll
            for (int i = 0; i < 4; i++) {
                va0[i] = *(const float4*)(pA0 + o + i * 4);
                va1[i] = *(const float4*)(pA1 + o + i * 4);
                vw[i]  = *(const float4*)(pW  + o + i * 4);
            }
        }
        __syncthreads();   // chunk c stores visible; mma(c-1) done everywhere

        const uint32_t st = sbase + bufB;
#pragma unroll
        for (int ks = 0; ks < 2; ks++) {
            const uint32_t kb = (uint32_t)(ks * 32);
            uint32_t ah[4][4], al[4][4];
#pragma unroll
            for (int mi = 0; mi < 4; mi++) {
                const uint32_t off = aOff + (uint32_t)(mi * 16 * PITCH * 2) + kb;
                ldm_x4(ah[mi], st + off);
                ldm_x4(al[mi], st + A_ARR + off);
            }
#pragma unroll
            for (int njh = 0; njh < 2; njh++) {
                uint32_t bh[2][4], bl[2][4];
#pragma unroll
                for (int pj = 0; pj < 2; pj++) {
                    const uint32_t off =
                        bOff + (uint32_t)((njh * 2 + pj) * 16 * PITCH * 2) + kb;
                    ldm_x4(bh[pj], st + 2 * A_ARR + off);
                    ldm_x4(bl[pj], st + 2 * A_ARR + W_ARR + off);
                }
#pragma unroll
                for (int mi = 0; mi < 4; mi++)
#pragma unroll
                    for (int njl = 0; njl < 4; njl++) {
                        float* a4 = acc[mi][njh * 4 + njl];
                        const uint32_t* bhp = &bh[njl >> 1][(njl & 1) * 2];
                        const uint32_t* blp = &bl[njl >> 1][(njl & 1) * 2];
                        mma_bf16(a4, ah[mi], bhp);
                        mma_bf16(a4, al[mi], bhp);
                        mma_bf16(a4, ah[mi], blp);
                    }
            }
        }
    }

    // Epilogue
    const int t4 = lid >> 2;
    const int t2 = (lid & 3) << 1;
    if (EPI == 1) {
        const int seg = n0 >> 7;
        const int hh = (int)((unsigned)seg / 3u);
        const int which = seg - hh * 3;
        __nv_bfloat16 *hib, *lob;
        float* fpb = nullptr;
        if (which == 0)      { hib = g_qhi; lob = g_qlo; }
        else if (which == 1) { hib = g_khi; lob = g_klo; fpb = kout; }
        else                 { hib = g_vhi; lob = g_vlo; fpb = vout; }
        const float scl = (which == 0) ? 0.08838834764831845f : 1.0f;
#pragma unroll
        for (int mi = 0; mi < 4; mi++) {
            const int mrow = m0 + warpM * 64 + mi * 16 + t4;
            const int bb = mrow >> 11, ss = mrow & 2047;
            const size_t i0 = (((size_t)(bb * NHEAD + hh)) * SLEN + ss) * HS;
            const size_t i1 = i0 + 8 * HS;
#pragma unroll
            for (int nj = 0; nj < 8; nj++) {
                const int col = warpN * 64 + nj * 8 + t2;
                const float2 bv = *(const float2*)(bias + n0 + col);
                float x0 = acc[mi][nj][0] + bv.x, x1 = acc[mi][nj][1] + bv.y;
                float y0 = acc[mi][nj][2] + bv.x, y1 = acc[mi][nj][3] + bv.y;
                if (which != 0) {
                    *(float2*)(fpb + i0 + col) = make_float2(x0, x1);
                    *(float2*)(fpb + i1 + col) = make_float2(y0, y1);
                }
                x0 *= scl; x1 *= scl; y0 *= scl; y1 *= scl;
                __nv_bfloat162 hx = __floats2bfloat162_rn(x0, x1);
                float2 hf = __bfloat1622float2(hx);
                __nv_bfloat162 lx = __floats2bfloat162_rn(x0 - hf.x, x1 - hf.y);
                __nv_bfloat162 hy = __floats2bfloat162_rn(y0, y1);
                float2 hg = __bfloat1622float2(hy);
                __nv_bfloat162 ly = __floats2bfloat162_rn(y0 - hg.x, y1 - hg.y);
                *(__nv_bfloat162*)(hib + i0 + col) = hx;
                *(__nv_bfloat162*)(lob + i0 + col) = lx;
                *(__nv_bfloat162*)(hib + i1 + col) = hy;
                *(__nv_bfloat162*)(lob + i1 + col) = ly;
            }
        }
    } else {
#pragma unroll
        for (int mi = 0; mi < 4; mi++) {
            const int mrow = m0 + warpM * 64 + mi * 16 + t4;
            float* d0 = C + (size_t)mrow * DM + n0;
            float* d1 = C + (size_t)(mrow + 8) * DM + n0;
#pragma unroll
            for (int nj = 0; nj < 8; nj++) {
                const int col = warpN * 64 + nj * 8 + t2;
                const float2 bv = *(const float2*)(bias + n0 + col);
                *(float2*)(d0 + col) =
                    make_float2(acc[mi][nj][0] + bv.x, acc[mi][nj][1] + bv.y);
                *(float2*)(d1 + col) =
                    make_float2(acc[mi][nj][2] + bv.x, acc[mi][nj][3] + bv.y);
            }
        }
    }
}

// ---------------------------------------------------------------------------
// Flash attention via mma.sync (FA2-style), causal — unchanged from R13.
// ---------------------------------------------------------------------------
#define QT 128
#define KT 64
#define Q_BYTES 32768
#define KV_ARR 16384
#define KV_BUF (4 * KV_ARR)
#define ATT_SMEM (2 * Q_BYTES + 2 * KV_BUF)  // 196608

__device__ __forceinline__ uint32_t swz(int row, int chunk) {
    return (uint32_t)(row * 256 + ((chunk ^ (row & 7)) << 4));
}

__global__ __launch_bounds__(256) void attn_mma_kernel()
{
    extern __shared__ __align__(16) char sm[];
    const uint32_t sb = smem_u32(sm);
    const int tid = threadIdx.x, wid = tid >> 5, lane = tid & 31;
    const int qb = blockIdx.x, bh = blockIdx.y;
    const int q0 = qb * QT;
    const int nkt = 2 * qb + 2;

    const size_t qoff = ((size_t)bh * SLEN + q0) * HS;
    const size_t kvoff = (size_t)bh * SLEN * HS;

    {
        const int half = tid >> 7;
        const __nv_bfloat16* src = (half ? g_qlo : g_qhi) + qoff;
        char* base = sm + half * Q_BYTES;
        int rc = tid & 127;
#pragma unroll
        for (int t = 0; t < 16; t++, rc += 128) {
            const int row = rc >> 4, c = rc & 15;
            uint4 v = *(const uint4*)(src + row * HS + c * 8);
            *(uint4*)(base + swz(row, c)) = v;
        }
    }

    const int karr = tid >> 6;
    const __nv_bfloat16* ksrc =
        ((karr == 0) ? g_khi : (karr == 1) ? g_klo : (karr == 2) ? g_vhi : g_vlo)
        + kvoff;
    const uint32_t kdstArr = sb + 2 * Q_BYTES + (uint32_t)(karr * KV_ARR);

    auto kv_issue = [&](int kt, int bf) {
        const __nv_bfloat16* s = ksrc + (size_t)kt * KT * HS;
        const uint32_t dbase = kdstArr + (uint32_t)(bf * KV_BUF);
        int rc = tid & 63;
#pragma unroll
        for (int t = 0; t < 16; t++, rc += 64) {
            const int row = rc >> 4, c = rc & 15;
            CP_ASYNC16(dbase + swz(row, c), s + row * HS + c * 8);
        }
    };

    kv_issue(0, 0);
    CP_COMMIT();

    float o[16][4];
#pragma unroll
    for (int t = 0; t < 16; t++)
#pragma unroll
        for (int r = 0; r < 4; r++) o[t][r] = 0.f;
    float m0r = -INFINITY, m1r = -INFINITY, l0r = 0.f, l1r = 0.f;

    const int aRow = wid * 16 + (lane & 7) + ((lane >> 3) & 1) * 8;
    const int aCh = lane >> 4;
    const int bRowK = (lane & 7) + (lane >> 4) * 8;
    const int bChK = (lane >> 3) & 1;
    const int vRow = (lane & 7) + ((lane >> 3) & 1) * 8;
    const int vCh = lane >> 4;

    for (int kt = 0; kt < nkt; kt++) {
        if (kt + 1 < nkt) {
            kv_issue(kt + 1, (kt + 1) & 1);
            CP_COMMIT();
            CP_WAIT1();
        } else {
            CP_WAIT0();
        }
        __syncthreads();

        const uint32_t kvb = sb + 2 * Q_BYTES + (uint32_t)((kt & 1) * KV_BUF);

        float s[8][4];
#pragma unroll
        for (int nj = 0; nj < 8; nj++)
#pragma unroll
            for (int r = 0; r < 4; r++) s[nj][r] = 0.f;

#pragma unroll
        for (int ks = 0; ks < 8; ks++) {
            uint32_t qh[4], ql[4];
            const uint32_t qa = sb + swz(aRow, 2 * ks + aCh);
            ldm_x4(qh, qa);
            ldm_x4(ql, qa + Q_BYTES);
#pragma unroll
            for (int njp = 0; njp < 4; njp++) {
                uint32_t kh[4], kl[4];
                const uint32_t ka = kvb + swz(njp * 16 + bRowK, 2 * ks + bChK);
                ldm_x4(kh, ka);
                ldm_x4(kl, ka + KV_ARR);
                mma_bf16(s[2 * njp], qh, kh);
                mma_bf16(s[2 * njp], ql, kh);
                mma_bf16(s[2 * njp], qh, kl);
                mma_bf16(s[2 * njp + 1], qh, kh + 2);
                mma_bf16(s[2 * njp + 1], ql, kh + 2);
                mma_bf16(s[2 * njp + 1], qh, kl + 2);
            }
        }

        const int r0g = q0 + wid * 16 + (lane >> 2);
        if (kt >= 2 * qb) {
            const int cb = kt * KT + (lane & 3) * 2;
#pragma unroll
            for (int nj = 0; nj < 8; nj++) {
                const int c0 = cb + nj * 8;
                if (c0 > r0g)         s[nj][0] = -INFINITY;
                if (c0 + 1 > r0g)     s[nj][1] = -INFINITY;
                if (c0 > r0g + 8)     s[nj][2] = -INFINITY;
                if (c0 + 1 > r0g + 8) s[nj][3] = -INFINITY;
            }
        }

        float tm0 = -INFINITY, tm1 = -INFINITY;
#pragma unroll
        for (int nj = 0; nj < 8; nj++) {
            tm0 = fmaxf(tm0, fmaxf(s[nj][0], s[nj][1]));
            tm1 = fmaxf(tm1, fmaxf(s[nj][2], s[nj][3]));
        }
        tm0 = fmaxf(tm0, __shfl_xor_sync(0xffffffffu, tm0, 1));
        tm0 = fmaxf(tm0, __shfl_xor_sync(0xffffffffu, tm0, 2));
        tm1 = fmaxf(tm1, __shfl_xor_sync(0xffffffffu, tm1, 1));
        tm1 = fmaxf(tm1, __shfl_xor_sync(0xffffffffu, tm1, 2));
        const float mn0 = fmaxf(m0r, tm0), mn1 = fmaxf(m1r, tm1);
        const float a0 = __expf(m0r - mn0), a1 = __expf(m1r - mn1);
        m0r = mn0; m1r = mn1;

        float ls0 = 0.f, ls1 = 0.f;
        uint32_t pah[4][4], pal[4][4];
#pragma unroll
        for (int nj = 0; nj < 8; nj++) {
            const float p0 = __expf(s[nj][0] - mn0);
            const float p1 = __expf(s[nj][1] - mn0);
            const float p2 = __expf(s[nj][2] - mn1);
            const float p3 = __expf(s[nj][3] - mn1);
            ls0 += p0 + p1;
            ls1 += p2 + p3;
            __nv_bfloat162 h01 = __floats2bfloat162_rn(p0, p1);
            float2 hf01 = __bfloat1622float2(h01);
            __nv_bfloat162 lo01 = __floats2bfloat162_rn(p0 - hf01.x, p1 - hf01.y);
            __nv_bfloat162 h23 = __floats2bfloat162_rn(p2, p3);
            float2 hf23 = __bfloat1622float2(h23);
            __nv_bfloat162 lo23 = __floats2bfloat162_rn(p2 - hf23.x, p3 - hf23.y);
            const int j = nj >> 1, e = (nj & 1) * 2;
            pah[j][e] = *(uint32_t*)&h01;
            pah[j][e + 1] = *(uint32_t*)&h23;
            pal[j][e] = *(uint32_t*)&lo01;
            pal[j][e + 1] = *(uint32_t*)&lo23;
        }
        ls0 += __shfl_xor_sync(0xffffffffu, ls0, 1);
        ls0 += __shfl_xor_sync(0xffffffffu, ls0, 2);
        ls1 += __shfl_xor_sync(0xffffffffu, ls1, 1);
        ls1 += __shfl_xor_sync(0xffffffffu, ls1, 2);
        l0r = l0r * a0 + ls0;
        l1r = l1r * a1 + ls1;

#pragma unroll
        for (int t = 0; t < 16; t++) {
            o[t][0] *= a0; o[t][1] *= a0;
            o[t][2] *= a1; o[t][3] *= a1;
        }

#pragma unroll
        for (int j = 0; j < 4; j++) {
#pragma unroll
            for (int nd = 0; nd < 8; nd++) {
                uint32_t vh[4], vl[4];
                const uint32_t va =
                    kvb + 2 * KV_ARR + swz(j * 16 + vRow, 2 * nd + vCh);
                ldm_x4_t(vh, va);
                ldm_x4_t(vl, va + KV_ARR);
                mma_bf16(o[2 * nd], pah[j], vh);
                mma_bf16(o[2 * nd], pal[j], vh);
                mma_bf16(o[2 * nd], pah[j], vl);
                mma_bf16(o[2 * nd + 1], pah[j], vh + 2);
                mma_bf16(o[2 * nd + 1], pal[j], vh + 2);
                mma_bf16(o[2 * nd + 1], pah[j], vl + 2);
            }
        }
        __syncthreads();
    }

    // write attn_o (normalized, fp32) to g_attn [B,S,D]
    const float inv0 = 1.f / l0r, inv1 = 1.f / l1r;
    const int b = bh >> 4, h = bh & 15;
    const int r0g = q0 + wid * 16 + (lane >> 2);
    float* d0 = g_attn + ((size_t)(b * SLEN + r0g)) * DM + h * HS + (lane & 3) * 2;
    float* d1 = d0 + (size_t)8 * DM;
#pragma unroll
    for (int t = 0; t < 16; t++) {
        *(float2*)(d0 + t * 8) = make_float2(o[t][0] * inv0, o[t][1] * inv0);
        *(float2*)(d1 + t * 8) = make_float2(o[t][2] * inv1, o[t][3] * inv1);
    }
}

// ---------------------------------------------------------------------------
extern "C" void kernel_launch(void* const* d_in, const int* in_sizes, int n_in,
                              void* d_out, int out_size)
{
    const float* x      = (const float*)d_in[0];
    const float* w_proj = (const float*)d_in[1];
    const float* b_proj = (const float*)d_in[2];
    const float* w_ff   = (const float*)d_in[3];
    const float* b_ff   = (const float*)d_in[4];

    float* out = (float*)d_out;
    float* ff   = out;
    float* kout = out + (size_t)BATCH * SLEN * DM;
    float* vout = kout + (size_t)BATCH * NHEAD * SLEN * HS;

    cudaFuncSetAttribute(attn_mma_kernel,
                         cudaFuncAttributeMaxDynamicSharedMemorySize, ATT_SMEM);
    cudaFuncSetAttribute(gemm_mma_kernel<1>,
                         cudaFuncAttributeMaxDynamicSharedMemorySize, GEMM_SMEM);
    cudaFuncSetAttribute(gemm_mma_kernel<2>,
                         cudaFuncAttributeMaxDynamicSharedMemorySize, GEMM_SMEM);

    // 1) QKV projection: q(scaled) hi/lo -> scratch, k/v fp32 -> d_out + hi/lo
    gemm_mma_kernel<1><<<dim3(EPROJ / 128, (BATCH * SLEN) / 256), 256, GEMM_SMEM>>>(
        x, w_proj, b_proj, (float*)nullptr, kout, vout);

    // 2) Causal flash attention (mma.sync) -> g_attn
    attn_mma_kernel<<<dim3(SLEN / QT, BATCH * NHEAD), 256, ATT_SMEM>>>();

    // 3) FF projection -> ff output
    gemm_mma_kernel<2><<<dim3(DM / 128, (BATCH * SLEN) / 256), 256, GEMM_SMEM>>>(
        (const float*)nullptr, w_ff, b_ff, ff, (float*)nullptr, (float*)nullptr);
}

// round 15
// speedup vs baseline: 1.8852x; 1.0136x over previous
#include <cuda_runtime.h>
#include <cuda_bf16.h>
#include <math.h>
#include <stdint.h>

#define BATCH 4
#define SLEN 2048
#define DM 2048
#define NHEAD 16
#define HS 128
#define EPROJ (3 * DM)
#define KDIM 2048

// Scratch (no allocations allowed)
__device__ __nv_bfloat16 g_qhi[(size_t)BATCH * NHEAD * SLEN * HS];
__device__ __nv_bfloat16 g_qlo[(size_t)BATCH * NHEAD * SLEN * HS];
__device__ __nv_bfloat16 g_khi[(size_t)BATCH * NHEAD * SLEN * HS];
__device__ __nv_bfloat16 g_klo[(size_t)BATCH * NHEAD * SLEN * HS];
__device__ __nv_bfloat16 g_vhi[(size_t)BATCH * NHEAD * SLEN * HS];
__device__ __nv_bfloat16 g_vlo[(size_t)BATCH * NHEAD * SLEN * HS];
__device__ __nv_bfloat16 g_athi[(size_t)BATCH * SLEN * DM];
__device__ __nv_bfloat16 g_atlo[(size_t)BATCH * SLEN * DM];

// ---------------------------------------------------------------------------
// helpers (non-arch-specific PTX only)
// ---------------------------------------------------------------------------
__device__ __forceinline__ uint32_t smem_u32(const void* p) {
    uint32_t a;
    asm("{ .reg .u64 t; cvta.to.shared.u64 t, %1; cvt.u32.u64 %0, t; }"
        : "=r"(a) : "l"(p));
    return a;
}

__device__ __forceinline__ void ldm_x4(uint32_t* r, uint32_t addr) {
    asm volatile("ldmatrix.sync.aligned.m8n8.x4.shared.b16 {%0,%1,%2,%3}, [%4];"
                 : "=r"(r[0]), "=r"(r[1]), "=r"(r[2]), "=r"(r[3]) : "r"(addr));
}

__device__ __forceinline__ void ldm_x4_t(uint32_t* r, uint32_t addr) {
    asm volatile("ldmatrix.sync.aligned.m8n8.x4.trans.shared.b16 {%0,%1,%2,%3}, [%4];"
                 : "=r"(r[0]), "=r"(r[1]), "=r"(r[2]), "=r"(r[3]) : "r"(addr));
}

__device__ __forceinline__ void mma_bf16(float* c, const uint32_t* a,
                                         const uint32_t* b) {
    asm volatile(
        "mma.sync.aligned.m16n8k16.row.col.f32.bf16.bf16.f32 "
        "{%0,%1,%2,%3}, {%4,%5,%6,%7}, {%8,%9}, {%0,%1,%2,%3};"
        : "+f"(c[0]), "+f"(c[1]), "+f"(c[2]), "+f"(c[3])
        : "r"(a[0]), "r"(a[1]), "r"(a[2]), "r"(a[3]), "r"(b[0]), "r"(b[1]));
}

#define CP_ASYNC16(dst, src) \
    asm volatile("cp.async.cg.shared.global [%0], [%1], 16;" \
                 :: "r"(dst), "l"(src))
#define CP_COMMIT() asm volatile("cp.async.commit_group;" ::: "memory")
#define CP_WAIT1() asm volatile("cp.async.wait_group 1;" ::: "memory")
#define CP_WAIT0() asm volatile("cp.async.wait_group 0;" ::: "memory")

__device__ __forceinline__ void split4(float4 v, uint2& hi, uint2& lo) {
    __nv_bfloat162 h01 = __floats2bfloat162_rn(v.x, v.y);
    __nv_bfloat162 h23 = __floats2bfloat162_rn(v.z, v.w);
    uint32_t u01 = *(uint32_t*)&h01, u23 = *(uint32_t*)&h23;
    float fx = __uint_as_float(u01 << 16);
    float fy = __uint_as_float(u01 & 0xffff0000u);
    float fz = __uint_as_float(u23 << 16);
    float fw = __uint_as_float(u23 & 0xffff0000u);
    __nv_bfloat162 l01 = __floats2bfloat162_rn(v.x - fx, v.y - fy);
    __nv_bfloat162 l23 = __floats2bfloat162_rn(v.z - fz, v.w - fw);
    hi = make_uint2(u01, u23);
    lo = make_uint2(*(uint32_t*)&l01, *(uint32_t*)&l23);
}

// split a 16-float row-half and store packed as 2x uint4 hi + 2x uint4 lo
__device__ __forceinline__ void stage_row(const float4* v, char* hiDst,
                                          char* loDst) {
    uint2 h0, l0, h1, l1, h2, l2, h3, l3;
    split4(v[0], h0, l0);
    split4(v[1], h1, l1);
    split4(v[2], h2, l2);
    split4(v[3], h3, l3);
    *(uint4*)(hiDst)      = make_uint4(h0.x, h0.y, h1.x, h1.y);
    *(uint4*)(hiDst + 16) = make_uint4(h2.x, h2.y, h3.x, h3.y);
    *(uint4*)(loDst)      = make_uint4(l0.x, l0.y, l1.x, l1.y);
    *(uint4*)(loDst + 16) = make_uint4(l2.x, l2.y, l3.x, l3.y);
}

// ---------------------------------------------------------------------------
// mma.sync bf16-split GEMM: C = A * W^T + bias.
// CTA 256x128, 8 warps (4Mx2N), warp 64x64, BK=32, double-buffered smem,
// one sync per chunk, packed STS.128 staging.
// EPI==1: A = fp32 x (split in-kernel). QKV epilogue.
// EPI==2: A = g_athi/g_atlo (pre-split bf16, direct stores). Dense epilogue.
// W always fp32, split in-kernel.
// ---------------------------------------------------------------------------
#define PITCH 40
#define A_ARR (256 * PITCH * 2)        // 20480 B (Ahi / Alo each)
#define W_ARR (128 * PITCH * 2)        // 10240 B (Whi / Wlo each)
#define BUF_B (2 * A_ARR + 2 * W_ARR)  // 61440 B per buffer
#define GEMM_SMEM (2 * BUF_B)          // 122880 B

template <int EPI>
__global__ __launch_bounds__(256) void gemm_mma_kernel(
    const float* __restrict__ Ain, const float* __restrict__ W,
    const float* __restrict__ bias, float* __restrict__ C,
    float* __restrict__ kout, float* __restrict__ vout)
{
    extern __shared__ __align__(16) char sm_bf[];

    const int K = KDIM;
    const int tid = threadIdx.x;
    const int wid = tid >> 5;
    const int lid = tid & 31;
    const int m0 = blockIdx.y * 256;
    const int n0 = blockIdx.x * 128;
    const int warpM = wid >> 1;    // 0..3
    const int warpN = wid & 1;     // 0..1

    const uint32_t sbase = smem_u32(sm_bf);

    const int q = lid >> 3, rr = lid & 7;
    const uint32_t aOff =
        (uint32_t)(((warpM * 64 + (q & 1) * 8 + rr) * PITCH + (q >> 1) * 8) * 2);
    const uint32_t bOff =
        (uint32_t)(((warpN * 64 + (q >> 1) * 8 + rr) * PITCH + (q & 1) * 8) * 2);

    float acc[4][8][4];
#pragma unroll
    for (int i = 0; i < 4; i++)
#pragma unroll
        for (int j = 0; j < 8; j++)
#pragma unroll
            for (int r = 0; r < 4; r++) acc[i][j][r] = 0.f;

    // staging assignment: r = tid>>1 (0..127), half h = tid&1 (16 cols)
    const int r = tid >> 1;
    const int h = tid & 1;
    const float* pW = W + (size_t)(n0 + r) * K + h * 16;
    const uint32_t stoA0 = (uint32_t)(r * PITCH + h * 16);
    const uint32_t stoA1 = (uint32_t)((128 + r) * PITCH + h * 16);
    const uint32_t stoW  = stoA0;

    // fp32-A prefetch (EPI==1)
    const float* pA0f = Ain + (size_t)(m0 + r) * K + h * 16;
    const float* pA1f = Ain + (size_t)(m0 + 128 + r) * K + h * 16;
    float4 va0[4], va1[4], vw[4];
    // bf16-A prefetch (EPI==2)
    const __nv_bfloat16* pAh0 = g_athi + (size_t)(m0 + r) * K + h * 16;
    const __nv_bfloat16* pAl0 = g_atlo + (size_t)(m0 + r) * K + h * 16;
    const __nv_bfloat16* pAh1 = g_athi + (size_t)(m0 + 128 + r) * K + h * 16;
    const __nv_bfloat16* pAl1 = g_atlo + (size_t)(m0 + 128 + r) * K + h * 16;
    uint4 ra[8];

    if (EPI == 1) {
#pragma unroll
        for (int i = 0; i < 4; i++) {
            va0[i] = *(const float4*)(pA0f + i * 4);
            va1[i] = *(const float4*)(pA1f + i * 4);
        }
    } else {
        ra[0] = *(const uint4*)(pAh0);     ra[1] = *(const uint4*)(pAh0 + 8);
        ra[2] = *(const uint4*)(pAl0);     ra[3] = *(const uint4*)(pAl0 + 8);
        ra[4] = *(const uint4*)(pAh1);     ra[5] = *(const uint4*)(pAh1 + 8);
        ra[6] = *(const uint4*)(pAl1);     ra[7] = *(const uint4*)(pAl1 + 8);
    }
#pragma unroll
    for (int i = 0; i < 4; i++) vw[i] = *(const float4*)(pW + i * 4);

    for (int c = 0; c < 64; c++) {
        const uint32_t bufB = (uint32_t)((c & 1) * BUF_B);
        char* sb0 = sm_bf + bufB;
        if (EPI == 1) {
            stage_row(va0, sb0 + (size_t)stoA0 * 2,
                      sb0 + A_ARR + (size_t)stoA0 * 2);
            stage_row(va1, sb0 + (size_t)stoA1 * 2,
                      sb0 + A_ARR + (size_t)stoA1 * 2);
        } else {
            *(uint4*)(sb0 + (size_t)stoA0 * 2) = ra[0];
            *(uint4*)(sb0 + (size_t)stoA0 * 2 + 16) = ra[1];
            *(uint4*)(sb0 + A_ARR + (size_t)stoA0 * 2) = ra[2];
            *(uint4*)(sb0 + A_ARR + (size_t)stoA0 * 2 + 16) = ra[3];
            *(uint4*)(sb0 + (size_t)stoA1 * 2) = ra[4];
            *(uint4*)(sb0 + (size_t)stoA1 * 2 + 16) = ra[5];
            *(uint4*)(sb0 + A_ARR + (size_t)stoA1 * 2) = ra[6];
            *(uint4*)(sb0 + A_ARR + (size_t)stoA1 * 2 + 16) = ra[7];
        }
        stage_row(vw, sb0 + 2 * A_ARR + (size_t)stoW * 2,
                  sb0 + 2 * A_ARR + W_ARR + (size_t)stoW * 2);

        if (c < 63) {
            const int o = (c + 1) * 32;
            if (EPI == 1) {
#pragma unroll
                for (int i = 0; i < 4; i++) {
                    va0[i] = *(const float4*)(pA0f + o + i * 4);
                    va1[i] = *(const float4*)(pA1f + o + i * 4);
                }
            } else {
                ra[0] = *(const uint4*)(pAh0 + o);
                ra[1] = *(const uint4*)(pAh0 + o + 8);
                ra[2] = *(const uint4*)(pAl0 + o);
                ra[3] = *(const uint4*)(pAl0 + o + 8);
                ra[4] = *(const uint4*)(pAh1 + o);
                ra[5] = *(const uint4*)(pAh1 + o + 8);
                ra[6] = *(const uint4*)(pAl1 + o);
                ra[7] = *(const uint4*)(pAl1 + o + 8);
            }
#pragma unroll
            for (int i = 0; i < 4; i++) vw[i] = *(const float4*)(pW + o + i * 4);
        }
        __syncthreads();

        const uint32_t st = sbase + bufB;
#pragma unroll
        for (int ks = 0; ks < 2; ks++) {
            const uint32_t kb = (uint32_t)(ks * 32);
            uint32_t ah[4][4], al[4][4];
#pragma unroll
            for (int mi = 0; mi < 4; mi++) {
                const uint32_t off = aOff + (uint32_t)(mi * 16 * PITCH * 2) + kb;
                ldm_x4(ah[mi], st + off);
                ldm_x4(al[mi], st + A_ARR + off);
            }
#pragma unroll
            for (int njh = 0; njh < 2; njh++) {
                uint32_t bh[2][4], bl[2][4];
#pragma unroll
                for (int pj = 0; pj < 2; pj++) {
                    const uint32_t off =
                        bOff + (uint32_t)((njh * 2 + pj) * 16 * PITCH * 2) + kb;
                    ldm_x4(bh[pj], st + 2 * A_ARR + off);
                    ldm_x4(bl[pj], st + 2 * A_ARR + W_ARR + off);
                }
#pragma unroll
                for (int mi = 0; mi < 4; mi++)
#pragma unroll
                    for (int njl = 0; njl < 4; njl++) {
                        float* a4 = acc[mi][njh * 4 + njl];
                        const uint32_t* bhp = &bh[njl >> 1][(njl & 1) * 2];
                        const uint32_t* blp = &bl[njl >> 1][(njl & 1) * 2];
                        mma_bf16(a4, ah[mi], bhp);
                        mma_bf16(a4, al[mi], bhp);
                        mma_bf16(a4, ah[mi], blp);
                    }
            }
        }
    }

    // Epilogue
    const int t4 = lid >> 2;
    const int t2 = (lid & 3) << 1;
    if (EPI == 1) {
        const int seg = n0 >> 7;
        const int hh = (int)((unsigned)seg / 3u);
        const int which = seg - hh * 3;
        __nv_bfloat16 *hib, *lob;
        float* fpb = nullptr;
        if (which == 0)      { hib = g_qhi; lob = g_qlo; }
        else if (which == 1) { hib = g_khi; lob = g_klo; fpb = kout; }
        else                 { hib = g_vhi; lob = g_vlo; fpb = vout; }
        const float scl = (which == 0) ? 0.08838834764831845f : 1.0f;
#pragma unroll
        for (int mi = 0; mi < 4; mi++) {
            const int mrow = m0 + warpM * 64 + mi * 16 + t4;
            const int bb = mrow >> 11, ss = mrow & 2047;
            const size_t i0 = (((size_t)(bb * NHEAD + hh)) * SLEN + ss) * HS;
            const size_t i1 = i0 + 8 * HS;
#pragma unroll
            for (int nj = 0; nj < 8; nj++) {
                const int col = warpN * 64 + nj * 8 + t2;
                const float2 bv = *(const float2*)(bias + n0 + col);
                float x0 = acc[mi][nj][0] + bv.x, x1 = acc[mi][nj][1] + bv.y;
                float y0 = acc[mi][nj][2] + bv.x, y1 = acc[mi][nj][3] + bv.y;
                if (which != 0) {
                    *(float2*)(fpb + i0 + col) = make_float2(x0, x1);
                    *(float2*)(fpb + i1 + col) = make_float2(y0, y1);
                }
                x0 *= scl; x1 *= scl; y0 *= scl; y1 *= scl;
                __nv_bfloat162 hx = __floats2bfloat162_rn(x0, x1);
                float2 hf = __bfloat1622float2(hx);
                __nv_bfloat162 lx = __floats2bfloat162_rn(x0 - hf.x, x1 - hf.y);
                __nv_bfloat162 hy = __floats2bfloat162_rn(y0, y1);
                float2 hg = __bfloat1622float2(hy);
                __nv_bfloat162 ly = __floats2bfloat162_rn(y0 - hg.x, y1 - hg.y);
                *(__nv_bfloat162*)(hib + i0 + col) = hx;
                *(__nv_bfloat162*)(lob + i0 + col) = lx;
                *(__nv_bfloat162*)(hib + i1 + col) = hy;
                *(__nv_bfloat162*)(lob + i1 + col) = ly;
            }
        }
    } else {
#pragma unroll
        for (int mi = 0; mi < 4; mi++) {
            const int mrow = m0 + warpM * 64 + mi * 16 + t4;
            float* d0 = C + (size_t)mrow * DM + n0;
            float* d1 = C + (size_t)(mrow + 8) * DM + n0;
#pragma unroll
            for (int nj = 0; nj < 8; nj++) {
                const int col = warpN * 64 + nj * 8 + t2;
                const float2 bv = *(const float2*)(bias + n0 + col);
                *(float2*)(d0 + col) =
                    make_float2(acc[mi][nj][0] + bv.x, acc[mi][nj][1] + bv.y);
                *(float2*)(d1 + col) =
                    make_float2(acc[mi][nj][2] + bv.x, acc[mi][nj][3] + bv.y);
            }
        }
    }
}

// ---------------------------------------------------------------------------
// Flash attention via mma.sync (FA2-style), causal; epilogue -> bf16 hi/lo.
// ---------------------------------------------------------------------------
#define QT 128
#define KT 64
#define Q_BYTES 32768
#define KV_ARR 16384
#define KV_BUF (4 * KV_ARR)
#define ATT_SMEM (2 * Q_BYTES + 2 * KV_BUF)  // 196608

__device__ __forceinline__ uint32_t swz(int row, int chunk) {
    return (uint32_t)(row * 256 + ((chunk ^ (row & 7)) << 4));
}

__global__ __launch_bounds__(256) void attn_mma_kernel()
{
    extern __shared__ __align__(16) char sm[];
    const uint32_t sb = smem_u32(sm);
    const int tid = threadIdx.x, wid = tid >> 5, lane = tid & 31;
    const int qb = blockIdx.x, bh = blockIdx.y;
    const int q0 = qb * QT;
    const int nkt = 2 * qb + 2;

    const size_t qoff = ((size_t)bh * SLEN + q0) * HS;
    const size_t kvoff = (size_t)bh * SLEN * HS;

    {
        const int half = tid >> 7;
        const __nv_bfloat16* src = (half ? g_qlo : g_qhi) + qoff;
        char* base = sm + half * Q_BYTES;
        int rc = tid & 127;
#pragma unroll
        for (int t = 0; t < 16; t++, rc += 128) {
            const int row = rc >> 4, c = rc & 15;
            uint4 v = *(const uint4*)(src + row * HS + c * 8);
            *(uint4*)(base + swz(row, c)) = v;
        }
    }

    const int karr = tid >> 6;
    const __nv_bfloat16* ksrc =
        ((karr == 0) ? g_khi : (karr == 1) ? g_klo : (karr == 2) ? g_vhi : g_vlo)
        + kvoff;
    const uint32_t kdstArr = sb + 2 * Q_BYTES + (uint32_t)(karr * KV_ARR);

    auto kv_issue = [&](int kt, int bf) {
        const __nv_bfloat16* s = ksrc + (size_t)kt * KT * HS;
        const uint32_t dbase = kdstArr + (uint32_t)(bf * KV_BUF);
        int rc = tid & 63;
#pragma unroll
        for (int t = 0; t < 16; t++, rc += 64) {
            const int row = rc >> 4, c = rc & 15;
            CP_ASYNC16(dbase + swz(row, c), s + row * HS + c * 8);
        }
    };

    kv_issue(0, 0);
    CP_COMMIT();

    float o[16][4];
#pragma unroll
    for (int t = 0; t < 16; t++)
#pragma unroll
        for (int r = 0; r < 4; r++) o[t][r] = 0.f;
    float m0r = -INFINITY, m1r = -INFINITY, l0r = 0.f, l1r = 0.f;

    const int aRow = wid * 16 + (lane & 7) + ((lane >> 3) & 1) * 8;
    const int aCh = lane >> 4;
    const int bRowK = (lane & 7) + (lane >> 4) * 8;
    const int bChK = (lane >> 3) & 1;
    const int vRow = (lane & 7) + ((lane >> 3) & 1) * 8;
    const int vCh = lane >> 4;

    for (int kt = 0; kt < nkt; kt++) {
        if (kt + 1 < nkt) {
            kv_issue(kt + 1, (kt + 1) & 1);
            CP_COMMIT();
            CP_WAIT1();
        } else {
            CP_WAIT0();
        }
        __syncthreads();

        const uint32_t kvb = sb + 2 * Q_BYTES + (uint32_t)((kt & 1) * KV_BUF);

        float s[8][4];
#pragma unroll
        for (int nj = 0; nj < 8; nj++)
#pragma unroll
            for (int r = 0; r < 4; r++) s[nj][r] = 0.f;

#pragma unroll
        for (int ks = 0; ks < 8; ks++) {
            uint32_t qh[4], ql[4];
            const uint32_t qa = sb + swz(aRow, 2 * ks + aCh);
            ldm_x4(qh, qa);
            ldm_x4(ql, qa + Q_BYTES);
#pragma unroll
            for (int njp = 0; njp < 4; njp++) {
                uint32_t kh[4], kl[4];
                const uint32_t ka = kvb + swz(njp * 16 + bRowK, 2 * ks + bChK);
                ldm_x4(kh, ka);
                ldm_x4(kl, ka + KV_ARR);
                mma_bf16(s[2 * njp], qh, kh);
                mma_bf16(s[2 * njp], ql, kh);
                mma_bf16(s[2 * njp], qh, kl);
                mma_bf16(s[2 * njp + 1], qh, kh + 2);
                mma_bf16(s[2 * njp + 1], ql, kh + 2);
                mma_bf16(s[2 * njp + 1], qh, kl + 2);
            }
        }

        const int r0g = q0 + wid * 16 + (lane >> 2);
        if (kt >= 2 * qb) {
            const int cb = kt * KT + (lane & 3) * 2;
#pragma unroll
            for (int nj = 0; nj < 8; nj++) {
                const int c0 = cb + nj * 8;
                if (c0 > r0g)         s[nj][0] = -INFINITY;
                if (c0 + 1 > r0g)     s[nj][1] = -INFINITY;
                if (c0 > r0g + 8)     s[nj][2] = -INFINITY;
                if (c0 + 1 > r0g + 8) s[nj][3] = -INFINITY;
            }
        }

        float tm0 = -INFINITY, tm1 = -INFINITY;
#pragma unroll
        for (int nj = 0; nj < 8; nj++) {
            tm0 = fmaxf(tm0, fmaxf(s[nj][0], s[nj][1]));
            tm1 = fmaxf(tm1, fmaxf(s[nj][2], s[nj][3]));
        }
        tm0 = fmaxf(tm0, __shfl_xor_sync(0xffffffffu, tm0, 1));
        tm0 = fmaxf(tm0, __shfl_xor_sync(0xffffffffu, tm0, 2));
        tm1 = fmaxf(tm1, __shfl_xor_sync(0xffffffffu, tm1, 1));
        tm1 = fmaxf(tm1, __shfl_xor_sync(0xffffffffu, tm1, 2));
        const float mn0 = fmaxf(m0r, tm0), mn1 = fmaxf(m1r, tm1);
        const float a0 = __expf(m0r - mn0), a1 = __expf(m1r - mn1);
        m0r = mn0; m1r = mn1;

        float ls0 = 0.f, ls1 = 0.f;
        uint32_t pah[4][4], pal[4][4];
#pragma unroll
        for (int nj = 0; nj < 8; nj++) {
            const float p0 = __expf(s[nj][0] - mn0);
            const float p1 = __expf(s[nj][1] - mn0);
            const float p2 = __expf(s[nj][2] - mn1);
            const float p3 = __expf(s[nj][3] - mn1);
            ls0 += p0 + p1;
            ls1 += p2 + p3;
            __nv_bfloat162 h01 = __floats2bfloat162_rn(p0, p1);
            float2 hf01 = __bfloat1622float2(h01);
            __nv_bfloat162 lo01 = __floats2bfloat162_rn(p0 - hf01.x, p1 - hf01.y);
            __nv_bfloat162 h23 = __floats2bfloat162_rn(p2, p3);
            float2 hf23 = __bfloat1622float2(h23);
            __nv_bfloat162 lo23 = __floats2bfloat162_rn(p2 - hf23.x, p3 - hf23.y);
            const int j = nj >> 1, e = (nj & 1) * 2;
            pah[j][e] = *(uint32_t*)&h01;
            pah[j][e + 1] = *(uint32_t*)&h23;
            pal[j][e] = *(uint32_t*)&lo01;
            pal[j][e + 1] = *(uint32_t*)&lo23;
        }
        ls0 += __shfl_xor_sync(0xffffffffu, ls0, 1);
        ls0 += __shfl_xor_sync(0xffffffffu, ls0, 2);
        ls1 += __shfl_xor_sync(0xffffffffu, ls1, 1);
        ls1 += __shfl_xor_sync(0xffffffffu, ls1, 2);
        l0r = l0r * a0 + ls0;
        l1r = l1r * a1 + ls1;

#pragma unroll
        for (int t = 0; t < 16; t++) {
            o[t][0] *= a0; o[t][1] *= a0;
            o[t][2] *= a1; o[t][3] *= a1;
        }

#pragma unroll
        for (int j = 0; j < 4; j++) {
#pragma unroll
            for (int nd = 0; nd < 8; nd++) {
                uint32_t vh[4], vl[4];
                const uint32_t va =
                    kvb + 2 * KV_ARR + swz(j * 16 + vRow, 2 * nd + vCh);
                ldm_x4_t(vh, va);
                ldm_x4_t(vl, va + KV_ARR);
                mma_bf16(o[2 * nd], pah[j], vh);
                mma_bf16(o[2 * nd], pal[j], vh);
                mma_bf16(o[2 * nd], pah[j], vl);
                mma_bf16(o[2 * nd + 1], pah[j], vh + 2);
                mma_bf16(o[2 * nd + 1], pal[j], vh + 2);
                mma_bf16(o[2 * nd + 1], pah[j], vl + 2);
            }
        }
        __syncthreads();
    }

    // write attn_o as bf16 hi/lo (consumed by FF GEMM)
    const float inv0 = 1.f / l0r, inv1 = 1.f / l1r;
    const int b = bh >> 4, h = bh & 15;
    const int r0g = q0 + wid * 16 + (lane >> 2);
    const size_t base0 =
        ((size_t)(b * SLEN + r0g)) * DM + h * HS + (lane & 3) * 2;
    const size_t base1 = base0 + (size_t)8 * DM;
#pragma unroll
    for (int t = 0; t < 16; t++) {
        float v0 = o[t][0] * inv0, v1 = o[t][1] * inv0;
        float w0 = o[t][2] * inv1, w1 = o[t][3] * inv1;
        __nv_bfloat162 h0 = __floats2bfloat162_rn(v0, v1);
        float2 f0 = __bfloat1622float2(h0);
        __nv_bfloat162 l0 = __floats2bfloat162_rn(v0 - f0.x, v1 - f0.y);
        __nv_bfloat162 h1 = __floats2bfloat162_rn(w0, w1);
        float2 f1 = __bfloat1622float2(h1);
        __nv_bfloat162 l1 = __floats2bfloat162_rn(w0 - f1.x, w1 - f1.y);
        *(__nv_bfloat162*)(g_athi + base0 + t * 8) = h0;
        *(__nv_bfloat162*)(g_atlo + base0 + t * 8) = l0;
        *(__nv_bfloat162*)(g_athi + base1 + t * 8) = h1;
        *(__nv_bfloat162*)(g_atlo + base1 + t * 8) = l1;
    }
}

// ---------------------------------------------------------------------------
extern "C" void kernel_launch(void* const* d_in, const int* in_sizes, int n_in,
                              void* d_out, int out_size)
{
    const float* x      = (const float*)d_in[0];
    const float* w_proj = (const float*)d_in[1];
    const float* b_proj = (const float*)d_in[2];
    const float* w_ff   = (const float*)d_in[3];
    const float* b_ff   = (const float*)d_in[4];

    float* out = (float*)d_out;
    float* ff   = out;
    float* kout = out + (size_t)BATCH * SLEN * DM;
    float* vout = kout + (size_t)BATCH * NHEAD * SLEN * HS;

    cudaFuncSetAttribute(attn_mma_kernel,
                         cudaFuncAttributeMaxDynamicSharedMemorySize, ATT_SMEM);
    cudaFuncSetAttribute(gemm_mma_kernel<1>,
                         cudaFuncAttributeMaxDynamicSharedMemorySize, GEMM_SMEM);
    cudaFuncSetAttribute(gemm_mma_kernel<2>,
                         cudaFuncAttributeMaxDynamicSharedMemorySize, GEMM_SMEM);

    // 1) QKV projection: q(scaled) hi/lo -> scratch, k/v fp32 -> d_out + hi/lo
    gemm_mma_kernel<1><<<dim3(EPROJ / 128, (BATCH * SLEN) / 256), 256, GEMM_SMEM>>>(
        x, w_proj, b_proj, (float*)nullptr, kout, vout);

    // 2) Causal flash attention (mma.sync) -> g_athi/g_atlo
    attn_mma_kernel<<<dim3(SLEN / QT, BATCH * NHEAD), 256, ATT_SMEM>>>();

    // 3) FF projection (A pre-split bf16) -> ff output
    gemm_mma_kernel<2><<<dim3(DM / 128, (BATCH * SLEN) / 256), 256, GEMM_SMEM>>>(
        (const float*)nullptr, w_ff, b_ff, ff, (float*)nullptr, (float*)nullptr);
}

// round 16
// speedup vs baseline: 2.6784x; 1.4207x over previous
#include <cuda_runtime.h>
#include <cuda_fp16.h>
#include <math.h>
#include <stdint.h>

#define BATCH 4
#define SLEN 2048
#define DM 2048
#define NHEAD 16
#define HS 128
#define EPROJ (3 * DM)
#define KDIM 2048

// Scratch (no allocations allowed) — fp16 operands
__device__ __half g_qhi[(size_t)BATCH * NHEAD * SLEN * HS];
__device__ __half g_qlo[(size_t)BATCH * NHEAD * SLEN * HS];
__device__ __half g_kf[(size_t)BATCH * NHEAD * SLEN * HS];
__device__ __half g_vf[(size_t)BATCH * NHEAD * SLEN * HS];
__device__ __half g_athi[(size_t)BATCH * SLEN * DM];
__device__ __half g_atlo[(size_t)BATCH * SLEN * DM];

// ---------------------------------------------------------------------------
// helpers (non-arch-specific PTX only)
// ---------------------------------------------------------------------------
__device__ __forceinline__ uint32_t smem_u32(const void* p) {
    uint32_t a;
    asm("{ .reg .u64 t; cvta.to.shared.u64 t, %1; cvt.u32.u64 %0, t; }"
        : "=r"(a) : "l"(p));
    return a;
}

__device__ __forceinline__ void ldm_x4(uint32_t* r, uint32_t addr) {
    asm volatile("ldmatrix.sync.aligned.m8n8.x4.shared.b16 {%0,%1,%2,%3}, [%4];"
                 : "=r"(r[0]), "=r"(r[1]), "=r"(r[2]), "=r"(r[3]) : "r"(addr));
}

__device__ __forceinline__ void ldm_x4_t(uint32_t* r, uint32_t addr) {
    asm volatile("ldmatrix.sync.aligned.m8n8.x4.trans.shared.b16 {%0,%1,%2,%3}, [%4];"
                 : "=r"(r[0]), "=r"(r[1]), "=r"(r[2]), "=r"(r[3]) : "r"(addr));
}

__device__ __forceinline__ void mma_f16(float* c, const uint32_t* a,
                                        const uint32_t* b) {
    asm volatile(
        "mma.sync.aligned.m16n8k16.row.col.f32.f16.f16.f32 "
        "{%0,%1,%2,%3}, {%4,%5,%6,%7}, {%8,%9}, {%0,%1,%2,%3};"
        : "+f"(c[0]), "+f"(c[1]), "+f"(c[2]), "+f"(c[3])
        : "r"(a[0]), "r"(a[1]), "r"(a[2]), "r"(a[3]), "r"(b[0]), "r"(b[1]));
}

#define CP_ASYNC16(dst, src) \
    asm volatile("cp.async.cg.shared.global [%0], [%1], 16;" \
                 :: "r"(dst), "l"(src))
#define CP_COMMIT() asm volatile("cp.async.commit_group;" ::: "memory")
#define CP_WAIT1() asm volatile("cp.async.wait_group 1;" ::: "memory")
#define CP_WAIT0() asm volatile("cp.async.wait_group 0;" ::: "memory")

// fp32x4 -> fp16 hi/lo (2-term split, ~21-bit effective mantissa)
__device__ __forceinline__ void split4h(float4 v, uint2& hi, uint2& lo) {
    __half2 h01 = __floats2half2_rn(v.x, v.y);
    __half2 h23 = __floats2half2_rn(v.z, v.w);
    float2 f01 = __half22float2(h01);
    float2 f23 = __half22float2(h23);
    __half2 l01 = __floats2half2_rn(v.x - f01.x, v.y - f01.y);
    __half2 l23 = __floats2half2_rn(v.z - f23.x, v.w - f23.y);
    hi = make_uint2(*(uint32_t*)&h01, *(uint32_t*)&h23);
    lo = make_uint2(*(uint32_t*)&l01, *(uint32_t*)&l23);
}

// 16 floats -> hi/lo fp16, packed STS.128
__device__ __forceinline__ void stage_row_hl(const float4* v, char* hiDst,
                                             char* loDst) {
    uint2 h0, l0, h1, l1, h2, l2, h3, l3;
    split4h(v[0], h0, l0);
    split4h(v[1], h1, l1);
    split4h(v[2], h2, l2);
    split4h(v[3], h3, l3);
    *(uint4*)(hiDst)      = make_uint4(h0.x, h0.y, h1.x, h1.y);
    *(uint4*)(hiDst + 16) = make_uint4(h2.x, h2.y, h3.x, h3.y);
    *(uint4*)(loDst)      = make_uint4(l0.x, l0.y, l1.x, l1.y);
    *(uint4*)(loDst + 16) = make_uint4(l2.x, l2.y, l3.x, l3.y);
}

// 16 floats -> single fp16, packed STS.128
__device__ __forceinline__ void stage_row_s(const float4* v, char* dst) {
    __half2 a = __floats2half2_rn(v[0].x, v[0].y);
    __half2 b = __floats2half2_rn(v[0].z, v[0].w);
    __half2 c = __floats2half2_rn(v[1].x, v[1].y);
    __half2 d = __floats2half2_rn(v[1].z, v[1].w);
    *(uint4*)(dst) = make_uint4(*(uint32_t*)&a, *(uint32_t*)&b,
                                *(uint32_t*)&c, *(uint32_t*)&d);
    a = __floats2half2_rn(v[2].x, v[2].y);
    b = __floats2half2_rn(v[2].z, v[2].w);
    c = __floats2half2_rn(v[3].x, v[3].y);
    d = __floats2half2_rn(v[3].z, v[3].w);
    *(uint4*)(dst + 16) = make_uint4(*(uint32_t*)&a, *(uint32_t*)&b,
                                     *(uint32_t*)&c, *(uint32_t*)&d);
}

// ---------------------------------------------------------------------------
// fp16 2-product GEMM: C = A * W^T + bias.  A split hi/lo fp16, W single fp16.
// CTA 256x128, 8 warps (4Mx2N), warp 64x64, BK=32, double-buffered smem,
// one sync per chunk.
// EPI==1: A = fp32 x (split in-kernel). QKV epilogue.
// EPI==2: A = g_athi/g_atlo (pre-split fp16). Dense epilogue.
// ---------------------------------------------------------------------------
#define PITCH 40
#define A_ARR (256 * PITCH * 2)        // 20480 B (Ahi / Alo each)
#define W_ARR (128 * PITCH * 2)        // 10240 B (single Wf)
#define BUF_B (2 * A_ARR + W_ARR)      // 51200 B per buffer
#define GEMM_SMEM (2 * BUF_B)          // 102400 B

template <int EPI>
__global__ __launch_bounds__(256) void gemm_mma_kernel(
    const float* __restrict__ Ain, const float* __restrict__ W,
    const float* __restrict__ bias, float* __restrict__ C,
    float* __restrict__ kout, float* __restrict__ vout)
{
    extern __shared__ __align__(16) char sm_bf[];

    const int K = KDIM;
    const int tid = threadIdx.x;
    const int wid = tid >> 5;
    const int lid = tid & 31;
    const int m0 = blockIdx.y * 256;
    const int n0 = blockIdx.x * 128;
    const int warpM = wid >> 1;    // 0..3
    const int warpN = wid & 1;     // 0..1

    const uint32_t sbase = smem_u32(sm_bf);

    const int q = lid >> 3, rr = lid & 7;
    const uint32_t aOff =
        (uint32_t)(((warpM * 64 + (q & 1) * 8 + rr) * PITCH + (q >> 1) * 8) * 2);
    const uint32_t bOff =
        (uint32_t)(((warpN * 64 + (q >> 1) * 8 + rr) * PITCH + (q & 1) * 8) * 2);

    float acc[4][8][4];
#pragma unroll
    for (int i = 0; i < 4; i++)
#pragma unroll
        for (int j = 0; j < 8; j++)
#pragma unroll
            for (int r = 0; r < 4; r++) acc[i][j][r] = 0.f;

    // staging: r = tid>>1 (0..127), half h = tid&1 (16 cols)
    const int r = tid >> 1;
    const int h = tid & 1;
    const float* pW = W + (size_t)(n0 + r) * K + h * 16;
    const uint32_t stoA0 = (uint32_t)(r * PITCH + h * 16);
    const uint32_t stoA1 = (uint32_t)((128 + r) * PITCH + h * 16);
    const uint32_t stoW  = stoA0;

    const float* pA0f = Ain + (size_t)(m0 + r) * K + h * 16;
    const float* pA1f = Ain + (size_t)(m0 + 128 + r) * K + h * 16;
    float4 va0[4], va1[4], vw[4];
    const __half* pAh0 = g_athi + (size_t)(m0 + r) * K + h * 16;
    const __half* pAl0 = g_atlo + (size_t)(m0 + r) * K + h * 16;
    const __half* pAh1 = g_athi + (size_t)(m0 + 128 + r) * K + h * 16;
    const __half* pAl1 = g_atlo + (size_t)(m0 + 128 + r) * K + h * 16;
    uint4 ra[8];

    if (EPI == 1) {
#pragma unroll
        for (int i = 0; i < 4; i++) {
            va0[i] = *(const float4*)(pA0f + i * 4);
            va1[i] = *(const float4*)(pA1f + i * 4);
        }
    } else {
        ra[0] = *(const uint4*)(pAh0);     ra[1] = *(const uint4*)(pAh0 + 8);
        ra[2] = *(const uint4*)(pAl0);     ra[3] = *(const uint4*)(pAl0 + 8);
        ra[4] = *(const uint4*)(pAh1);     ra[5] = *(const uint4*)(pAh1 + 8);
        ra[6] = *(const uint4*)(pAl1);     ra[7] = *(const uint4*)(pAl1 + 8);
    }
#pragma unroll
    for (int i = 0; i < 4; i++) vw[i] = *(const float4*)(pW + i * 4);

    for (int c = 0; c < 64; c++) {
        const uint32_t bufB = (uint32_t)((c & 1) * BUF_B);
        char* sb0 = sm_bf + bufB;
        if (EPI == 1) {
            stage_row_hl(va0, sb0 + (size_t)stoA0 * 2,
                         sb0 + A_ARR + (size_t)stoA0 * 2);
            stage_row_hl(va1, sb0 + (size_t)stoA1 * 2,
                         sb0 + A_ARR + (size_t)stoA1 * 2);
        } else {
            *(uint4*)(sb0 + (size_t)stoA0 * 2) = ra[0];
            *(uint4*)(sb0 + (size_t)stoA0 * 2 + 16) = ra[1];
            *(uint4*)(sb0 + A_ARR + (size_t)stoA0 * 2) = ra[2];
            *(uint4*)(sb0 + A_ARR + (size_t)stoA0 * 2 + 16) = ra[3];
            *(uint4*)(sb0 + (size_t)stoA1 * 2) = ra[4];
            *(uint4*)(sb0 + (size_t)stoA1 * 2 + 16) = ra[5];
            *(uint4*)(sb0 + A_ARR + (size_t)stoA1 * 2) = ra[6];
            *(uint4*)(sb0 + A_ARR + (size_t)stoA1 * 2 + 16) = ra[7];
        }
        stage_row_s(vw, sb0 + 2 * A_ARR + (size_t)stoW * 2);

        if (c < 63) {
            const int o = (c + 1) * 32;
            if (EPI == 1) {
#pragma unroll
                for (int i = 0; i < 4; i++) {
                    va0[i] = *(const float4*)(pA0f + o + i * 4);
                    va1[i] = *(const float4*)(pA1f + o + i * 4);
                }
            } else {
                ra[0] = *(const uint4*)(pAh0 + o);
                ra[1] = *(const uint4*)(pAh0 + o + 8);
                ra[2] = *(const uint4*)(pAl0 + o);
                ra[3] = *(const uint4*)(pAl0 + o + 8);
                ra[4] = *(const uint4*)(pAh1 + o);
                ra[5] = *(const uint4*)(pAh1 + o + 8);
                ra[6] = *(const uint4*)(pAl1 + o);
                ra[7] = *(const uint4*)(pAl1 + o + 8);
            }
#pragma unroll
            for (int i = 0; i < 4; i++) vw[i] = *(const float4*)(pW + o + i * 4);
        }
        __syncthreads();

        const uint32_t st = sbase + bufB;
#pragma unroll
        for (int ks = 0; ks < 2; ks++) {
            const uint32_t kb = (uint32_t)(ks * 32);
            uint32_t ah[4][4], al[4][4];
#pragma unroll
            for (int mi = 0; mi < 4; mi++) {
                const uint32_t off = aOff + (uint32_t)(mi * 16 * PITCH * 2) + kb;
                ldm_x4(ah[mi], st + off);
                ldm_x4(al[mi], st + A_ARR + off);
            }
#pragma unroll
            for (int njh = 0; njh < 2; njh++) {
                uint32_t bf[2][4];
#pragma unroll
                for (int pj = 0; pj < 2; pj++) {
                    const uint32_t off =
                        bOff + (uint32_t)((njh * 2 + pj) * 16 * PITCH * 2) + kb;
                    ldm_x4(bf[pj], st + 2 * A_ARR + off);
                }
#pragma unroll
                for (int mi = 0; mi < 4; mi++)
#pragma unroll
                    for (int njl = 0; njl < 4; njl++) {
                        float* a4 = acc[mi][njh * 4 + njl];
                        const uint32_t* bfp = &bf[njl >> 1][(njl & 1) * 2];
                        mma_f16(a4, ah[mi], bfp);
                        mma_f16(a4, al[mi], bfp);
                    }
            }
        }
    }

    // Epilogue
    const int t4 = lid >> 2;
    const int t2 = (lid & 3) << 1;
    if (EPI == 1) {
        const int seg = n0 >> 7;
        const int hh = (int)((unsigned)seg / 3u);
        const int which = seg - hh * 3;
        const float scl = (which == 0) ? 0.08838834764831845f : 1.0f;
        float* fpb = (which == 1) ? kout : vout;
#pragma unroll
        for (int mi = 0; mi < 4; mi++) {
            const int mrow = m0 + warpM * 64 + mi * 16 + t4;
            const int bb = mrow >> 11, ss = mrow & 2047;
            const size_t i0 = (((size_t)(bb * NHEAD + hh)) * SLEN + ss) * HS;
            const size_t i1 = i0 + 8 * HS;
#pragma unroll
            for (int nj = 0; nj < 8; nj++) {
                const int col = warpN * 64 + nj * 8 + t2;
                const float2 bv = *(const float2*)(bias + n0 + col);
                float x0 = acc[mi][nj][0] + bv.x, x1 = acc[mi][nj][1] + bv.y;
                float y0 = acc[mi][nj][2] + bv.x, y1 = acc[mi][nj][3] + bv.y;
                if (which == 0) {
                    x0 *= scl; x1 *= scl; y0 *= scl; y1 *= scl;
                    __half2 hx = __floats2half2_rn(x0, x1);
                    float2 hf = __half22float2(hx);
                    __half2 lx = __floats2half2_rn(x0 - hf.x, x1 - hf.y);
                    __half2 hy = __floats2half2_rn(y0, y1);
                    float2 hg = __half22float2(hy);
                    __half2 ly = __floats2half2_rn(y0 - hg.x, y1 - hg.y);
                    *(__half2*)(g_qhi + i0 + col) = hx;
                    *(__half2*)(g_qlo + i0 + col) = lx;
                    *(__half2*)(g_qhi + i1 + col) = hy;
                    *(__half2*)(g_qlo + i1 + col) = ly;
                } else {
                    *(float2*)(fpb + i0 + col) = make_float2(x0, x1);
                    *(float2*)(fpb + i1 + col) = make_float2(y0, y1);
                    __half* hf16 = (which == 1) ? g_kf : g_vf;
                    *(__half2*)(hf16 + i0 + col) = __floats2half2_rn(x0, x1);
                    *(__half2*)(hf16 + i1 + col) = __floats2half2_rn(y0, y1);
                }
            }
        }
    } else {
#pragma unroll
        for (int mi = 0; mi < 4; mi++) {
            const int mrow = m0 + warpM * 64 + mi * 16 + t4;
            float* d0 = C + (size_t)mrow * DM + n0;
            float* d1 = C + (size_t)(mrow + 8) * DM + n0;
#pragma unroll
            for (int nj = 0; nj < 8; nj++) {
                const int col = warpN * 64 + nj * 8 + t2;
                const float2 bv = *(const float2*)(bias + n0 + col);
                *(float2*)(d0 + col) =
                    make_float2(acc[mi][nj][0] + bv.x, acc[mi][nj][1] + bv.y);
                *(float2*)(d1 + col) =
                    make_float2(acc[mi][nj][2] + bv.x, acc[mi][nj][3] + bv.y);
            }
        }
    }
}

// ---------------------------------------------------------------------------
// Flash attention via mma.sync, causal. fp16: Q split hi/lo, K single,
// P single, V single. CTA = 128 q-rows x one (b*H+h); KV tiles of 64,
// cp.async double-buffered. Epilogue -> fp16 hi/lo attn_o.
// ---------------------------------------------------------------------------
#define QT 128
#define KT 64
#define Q_BYTES 32768
#define KV_ARR 16384                      // one 64x128 fp16 tile
#define KV_BUF (2 * KV_ARR)               // kf + vf
#define ATT_SMEM (2 * Q_BYTES + 2 * KV_BUF)  // 131072

__device__ __forceinline__ uint32_t swz(int row, int chunk) {
    return (uint32_t)(row * 256 + ((chunk ^ (row & 7)) << 4));
}

__global__ __launch_bounds__(256) void attn_mma_kernel()
{
    extern __shared__ __align__(16) char sm[];
    const uint32_t sb = smem_u32(sm);
    const int tid = threadIdx.x, wid = tid >> 5, lane = tid & 31;
    const int qb = blockIdx.x, bh = blockIdx.y;
    const int q0 = qb * QT;
    const int nkt = 2 * qb + 2;

    const size_t qoff = ((size_t)bh * SLEN + q0) * HS;
    const size_t kvoff = (size_t)bh * SLEN * HS;

    {
        const int half = tid >> 7;
        const __half* src = (half ? g_qlo : g_qhi) + qoff;
        char* base = sm + half * Q_BYTES;
        int rc = tid & 127;
#pragma unroll
        for (int t = 0; t < 16; t++, rc += 128) {
            const int row = rc >> 4, c = rc & 15;
            uint4 v = *(const uint4*)(src + row * HS + c * 8);
            *(uint4*)(base + swz(row, c)) = v;
        }
    }

    const int karr = tid >> 7;   // 0: K, 1: V
    const __half* ksrc = ((karr == 0) ? g_kf : g_vf) + kvoff;
    const uint32_t kdstArr = sb + 2 * Q_BYTES + (uint32_t)(karr * KV_ARR);

    auto kv_issue = [&](int kt, int bf) {
        const __half* s = ksrc + (size_t)kt * KT * HS;
        const uint32_t dbase = kdstArr + (uint32_t)(bf * KV_BUF);
        int rc = tid & 127;
#pragma unroll
        for (int t = 0; t < 8; t++, rc += 128) {
            const int row = rc >> 4, c = rc & 15;
            CP_ASYNC16(dbase + swz(row, c), s + row * HS + c * 8);
        }
    };

    kv_issue(0, 0);
    CP_COMMIT();

    float o[16][4];
#pragma unroll
    for (int t = 0; t < 16; t++)
#pragma unroll
        for (int r = 0; r < 4; r++) o[t][r] = 0.f;
    float m0r = -INFINITY, m1r = -INFINITY, l0r = 0.f, l1r = 0.f;

    const int aRow = wid * 16 + (lane & 7) + ((lane >> 3) & 1) * 8;
    const int aCh = lane >> 4;
    const int bRowK = (lane & 7) + (lane >> 4) * 8;
    const int bChK = (lane >> 3) & 1;
    const int vRow = (lane & 7) + ((lane >> 3) & 1) * 8;
    const int vCh = lane >> 4;

    for (int kt = 0; kt < nkt; kt++) {
        if (kt + 1 < nkt) {
            kv_issue(kt + 1, (kt + 1) & 1);
            CP_COMMIT();
            CP_WAIT1();
        } else {
            CP_WAIT0();
        }
        __syncthreads();

        const uint32_t kvb = sb + 2 * Q_BYTES + (uint32_t)((kt & 1) * KV_BUF);

        float s[8][4];
#pragma unroll
        for (int nj = 0; nj < 8; nj++)
#pragma unroll
            for (int r = 0; r < 4; r++) s[nj][r] = 0.f;

#pragma unroll
        for (int ks = 0; ks < 8; ks++) {
            uint32_t qh[4], ql[4];
            const uint32_t qa = sb + swz(aRow, 2 * ks + aCh);
            ldm_x4(qh, qa);
            ldm_x4(ql, qa + Q_BYTES);
#pragma unroll
            for (int njp = 0; njp < 4; njp++) {
                uint32_t kf[4];
                const uint32_t ka = kvb + swz(njp * 16 + bRowK, 2 * ks + bChK);
                ldm_x4(kf, ka);
                mma_f16(s[2 * njp], qh, kf);
                mma_f16(s[2 * njp], ql, kf);
                mma_f16(s[2 * njp + 1], qh, kf + 2);
                mma_f16(s[2 * njp + 1], ql, kf + 2);
            }
        }

        const int r0g = q0 + wid * 16 + (lane >> 2);
        if (kt >= 2 * qb) {
            const int cb = kt * KT + (lane & 3) * 2;
#pragma unroll
            for (int nj = 0; nj < 8; nj++) {
                const int c0 = cb + nj * 8;
                if (c0 > r0g)         s[nj][0] = -INFINITY;
                if (c0 + 1 > r0g)     s[nj][1] = -INFINITY;
                if (c0 > r0g + 8)     s[nj][2] = -INFINITY;
                if (c0 + 1 > r0g + 8) s[nj][3] = -INFINITY;
            }
        }

        float tm0 = -INFINITY, tm1 = -INFINITY;
#pragma unroll
        for (int nj = 0; nj < 8; nj++) {
            tm0 = fmaxf(tm0, fmaxf(s[nj][0], s[nj][1]));
            tm1 = fmaxf(tm1, fmaxf(s[nj][2], s[nj][3]));
        }
        tm0 = fmaxf(tm0, __shfl_xor_sync(0xffffffffu, tm0, 1));
        tm0 = fmaxf(tm0, __shfl_xor_sync(0xffffffffu, tm0, 2));
        tm1 = fmaxf(tm1, __shfl_xor_sync(0xffffffffu, tm1, 1));
        tm1 = fmaxf(tm1, __shfl_xor_sync(0xffffffffu, tm1, 2));
        const float mn0 = fmaxf(m0r, tm0), mn1 = fmaxf(m1r, tm1);
        const float a0 = __expf(m0r - mn0), a1 = __expf(m1r - mn1);
        m0r = mn0; m1r = mn1;

        float ls0 = 0.f, ls1 = 0.f;
        uint32_t pa[4][4];
#pragma unroll
        for (int nj = 0; nj < 8; nj++) {
            const float p0 = __expf(s[nj][0] - mn0);
            const float p1 = __expf(s[nj][1] - mn0);
            const float p2 = __expf(s[nj][2] - mn1);
            const float p3 = __expf(s[nj][3] - mn1);
            ls0 += p0 + p1;
            ls1 += p2 + p3;
            __half2 h01 = __floats2half2_rn(p0, p1);
            __half2 h23 = __floats2half2_rn(p2, p3);
            const int j = nj >> 1, e = (nj & 1) * 2;
            pa[j][e] = *(uint32_t*)&h01;
            pa[j][e + 1] = *(uint32_t*)&h23;
        }
        ls0 += __shfl_xor_sync(0xffffffffu, ls0, 1);
        ls0 += __shfl_xor_sync(0xffffffffu, ls0, 2);
        ls1 += __shfl_xor_sync(0xffffffffu, ls1, 1);
        ls1 += __shfl_xor_sync(0xffffffffu, ls1, 2);
        l0r = l0r * a0 + ls0;
        l1r = l1r * a1 + ls1;

#pragma unroll
        for (int t = 0; t < 16; t++) {
            o[t][0] *= a0; o[t][1] *= a0;
            o[t][2] *= a1; o[t][3] *= a1;
        }

#pragma unroll
        for (int j = 0; j < 4; j++) {
#pragma unroll
            for (int nd = 0; nd < 8; nd++) {
                uint32_t vf[4];
                const uint32_t va =
                    kvb + KV_ARR + swz(j * 16 + vRow, 2 * nd + vCh);
                ldm_x4_t(vf, va);
                mma_f16(o[2 * nd], pa[j], vf);
                mma_f16(o[2 * nd + 1], pa[j], vf + 2);
            }
        }
        __syncthreads();
    }

    // write attn_o as fp16 hi/lo (consumed by FF GEMM)
    const float inv0 = 1.f / l0r, inv1 = 1.f / l1r;
    const int b = bh >> 4, h = bh & 15;
    const int r0g = q0 + wid * 16 + (lane >> 2);
    const size_t base0 =
        ((size_t)(b * SLEN + r0g)) * DM + h * HS + (lane & 3) * 2;
    const size_t base1 = base0 + (size_t)8 * DM;
#pragma unroll
    for (int t = 0; t < 16; t++) {
        float v0 = o[t][0] * inv0, v1 = o[t][1] * inv0;
        float w0 = o[t][2] * inv1, w1 = o[t][3] * inv1;
        __half2 h0 = __floats2half2_rn(v0, v1);
        float2 f0 = __half22float2(h0);
        __half2 l0 = __floats2half2_rn(v0 - f0.x, v1 - f0.y);
        __half2 h1 = __floats2half2_rn(w0, w1);
        float2 f1 = __half22float2(h1);
        __half2 l1 = __floats2half2_rn(w0 - f1.x, w1 - f1.y);
        *(__half2*)(g_athi + base0 + t * 8) = h0;
        *(__half2*)(g_atlo + base0 + t * 8) = l0;
        *(__half2*)(g_athi + base1 + t * 8) = h1;
        *(__half2*)(g_atlo + base1 + t * 8) = l1;
    }
}

// ---------------------------------------------------------------------------
extern "C" void kernel_launch(void* const* d_in, const int* in_sizes, int n_in,
                              void* d_out, int out_size)
{
    const float* x      = (const float*)d_in[0];
    const float* w_proj = (const float*)d_in[1];
    const float* b_proj = (const float*)d_in[2];
    const float* w_ff   = (const float*)d_in[3];
    const float* b_ff   = (const float*)d_in[4];

    float* out = (float*)d_out;
    float* ff   = out;
    float* kout = out + (size_t)BATCH * SLEN * DM;
    float* vout = kout + (size_t)BATCH * NHEAD * SLEN * HS;

    cudaFuncSetAttribute(attn_mma_kernel,
                         cudaFuncAttributeMaxDynamicSharedMemorySize, ATT_SMEM);
    cudaFuncSetAttribute(gemm_mma_kernel<1>,
                         cudaFuncAttributeMaxDynamicSharedMemorySize, GEMM_SMEM);
    cudaFuncSetAttribute(gemm_mma_kernel<2>,
                         cudaFuncAttributeMaxDynamicSharedMemorySize, GEMM_SMEM);

    // 1) QKV projection: q(scaled) fp16 hi/lo, k/v fp32 d_out + fp16 scratch
    gemm_mma_kernel<1><<<dim3(EPROJ / 128, (BATCH * SLEN) / 256), 256, GEMM_SMEM>>>(
        x, w_proj, b_proj, (float*)nullptr, kout, vout);

    // 2) Causal flash attention (fp16 mma.sync) -> g_athi/g_atlo
    attn_mma_kernel<<<dim3(SLEN / QT, BATCH * NHEAD), 256, ATT_SMEM>>>();

    // 3) FF projection (A pre-split fp16) -> ff output
    gemm_mma_kernel<2><<<dim3(DM / 128, (BATCH * SLEN) / 256), 256, GEMM_SMEM>>>(
        (const float*)nullptr, w_ff, b_ff, ff, (float*)nullptr, (float*)nullptr);
}

// round 17
// speedup vs baseline: 2.7561x; 1.0290x over previous
#include <cuda_runtime.h>
#include <cuda_fp16.h>
#include <math.h>
#include <stdint.h>

#define BATCH 4
#define SLEN 2048
#define DM 2048
#define NHEAD 16
#define HS 128
#define EPROJ (3 * DM)
#define KDIM 2048

// Scratch (no allocations allowed) — fp16 operands
__device__ __half g_qhi[(size_t)BATCH * NHEAD * SLEN * HS];
__device__ __half g_qlo[(size_t)BATCH * NHEAD * SLEN * HS];
__device__ __half g_kf[(size_t)BATCH * NHEAD * SLEN * HS];
__device__ __half g_vf[(size_t)BATCH * NHEAD * SLEN * HS];
__device__ __half g_athi[(size_t)BATCH * SLEN * DM];
__device__ __half g_atlo[(size_t)BATCH * SLEN * DM];
__device__ __half g_wpf[(size_t)EPROJ * DM];   // w_proj as fp16
__device__ __half g_wff[(size_t)DM * DM];      // w_ff as fp16

// ---------------------------------------------------------------------------
// helpers (non-arch-specific PTX only)
// ---------------------------------------------------------------------------
__device__ __forceinline__ uint32_t smem_u32(const void* p) {
    uint32_t a;
    asm("{ .reg .u64 t; cvta.to.shared.u64 t, %1; cvt.u32.u64 %0, t; }"
        : "=r"(a) : "l"(p));
    return a;
}

__device__ __forceinline__ void ldm_x4(uint32_t* r, uint32_t addr) {
    asm volatile("ldmatrix.sync.aligned.m8n8.x4.shared.b16 {%0,%1,%2,%3}, [%4];"
                 : "=r"(r[0]), "=r"(r[1]), "=r"(r[2]), "=r"(r[3]) : "r"(addr));
}

__device__ __forceinline__ void ldm_x4_t(uint32_t* r, uint32_t addr) {
    asm volatile("ldmatrix.sync.aligned.m8n8.x4.trans.shared.b16 {%0,%1,%2,%3}, [%4];"
                 : "=r"(r[0]), "=r"(r[1]), "=r"(r[2]), "=r"(r[3]) : "r"(addr));
}

__device__ __forceinline__ void mma_f16(float* c, const uint32_t* a,
                                        const uint32_t* b) {
    asm volatile(
        "mma.sync.aligned.m16n8k16.row.col.f32.f16.f16.f32 "
        "{%0,%1,%2,%3}, {%4,%5,%6,%7}, {%8,%9}, {%0,%1,%2,%3};"
        : "+f"(c[0]), "+f"(c[1]), "+f"(c[2]), "+f"(c[3])
        : "r"(a[0]), "r"(a[1]), "r"(a[2]), "r"(a[3]), "r"(b[0]), "r"(b[1]));
}

#define CP_ASYNC16(dst, src) \
    asm volatile("cp.async.cg.shared.global [%0], [%1], 16;" \
                 :: "r"(dst), "l"(src))
#define CP_COMMIT() asm volatile("cp.async.commit_group;" ::: "memory")
#define CP_WAIT1() asm volatile("cp.async.wait_group 1;" ::: "memory")
#define CP_WAIT0() asm volatile("cp.async.wait_group 0;" ::: "memory")

// fp32x4 -> fp16 hi/lo (2-term split)
__device__ __forceinline__ void split4h(float4 v, uint2& hi, uint2& lo) {
    __half2 h01 = __floats2half2_rn(v.x, v.y);
    __half2 h23 = __floats2half2_rn(v.z, v.w);
    float2 f01 = __half22float2(h01);
    float2 f23 = __half22float2(h23);
    __half2 l01 = __floats2half2_rn(v.x - f01.x, v.y - f01.y);
    __half2 l23 = __floats2half2_rn(v.z - f23.x, v.w - f23.y);
    hi = make_uint2(*(uint32_t*)&h01, *(uint32_t*)&h23);
    lo = make_uint2(*(uint32_t*)&l01, *(uint32_t*)&l23);
}

// 16 floats -> hi/lo fp16, packed STS.128
__device__ __forceinline__ void stage_row_hl(const float4* v, char* hiDst,
                                             char* loDst) {
    uint2 h0, l0, h1, l1, h2, l2, h3, l3;
    split4h(v[0], h0, l0);
    split4h(v[1], h1, l1);
    split4h(v[2], h2, l2);
    split4h(v[3], h3, l3);
    *(uint4*)(hiDst)      = make_uint4(h0.x, h0.y, h1.x, h1.y);
    *(uint4*)(hiDst + 16) = make_uint4(h2.x, h2.y, h3.x, h3.y);
    *(uint4*)(loDst)      = make_uint4(l0.x, l0.y, l1.x, l1.y);
    *(uint4*)(loDst + 16) = make_uint4(l2.x, l2.y, l3.x, l3.y);
}

// fp32 -> fp16 single, elementwise convert (bit-identical to in-kernel rn)
__global__ __launch_bounds__(256) void conv_kernel(
    const float4* __restrict__ src, uint2* __restrict__ dst, int n4)
{
    int i = blockIdx.x * 256 + threadIdx.x;
    const int stride = gridDim.x * 256;
    for (; i < n4; i += stride) {
        float4 v = src[i];
        __half2 a = __floats2half2_rn(v.x, v.y);
        __half2 b = __floats2half2_rn(v.z, v.w);
        dst[i] = make_uint2(*(uint32_t*)&a, *(uint32_t*)&b);
    }
}

// ---------------------------------------------------------------------------
// fp16 2-product GEMM: C = A * W^T + bias.  A split hi/lo fp16, W single fp16
// (pre-converted in global). CTA 256x128, 8 warps (4Mx2N), warp 64x64, BK=32,
// double-buffered smem, one sync per chunk.
// EPI==1: A = fp32 x (split in-kernel). QKV epilogue.
// EPI==2: A = g_athi/g_atlo (pre-split fp16). Dense epilogue.
// ---------------------------------------------------------------------------
#define PITCH 40
#define A_ARR (256 * PITCH * 2)        // 20480 B (Ahi / Alo each)
#define W_ARR (128 * PITCH * 2)        // 10240 B (single Wf)
#define BUF_B (2 * A_ARR + W_ARR)      // 51200 B per buffer
#define GEMM_SMEM (2 * BUF_B)          // 102400 B

template <int EPI>
__global__ __launch_bounds__(256) void gemm_mma_kernel(
    const float* __restrict__ Ain, const __half* __restrict__ Wf,
    const float* __restrict__ bias, float* __restrict__ C,
    float* __restrict__ kout, float* __restrict__ vout)
{
    extern __shared__ __align__(16) char sm_bf[];

    const int K = KDIM;
    const int tid = threadIdx.x;
    const int wid = tid >> 5;
    const int lid = tid & 31;
    const int m0 = blockIdx.y * 256;
    const int n0 = blockIdx.x * 128;
    const int warpM = wid >> 1;    // 0..3
    const int warpN = wid & 1;     // 0..1

    const uint32_t sbase = smem_u32(sm_bf);

    const int q = lid >> 3, rr = lid & 7;
    const uint32_t aOff =
        (uint32_t)(((warpM * 64 + (q & 1) * 8 + rr) * PITCH + (q >> 1) * 8) * 2);
    const uint32_t bOff =
        (uint32_t)(((warpN * 64 + (q >> 1) * 8 + rr) * PITCH + (q & 1) * 8) * 2);

    float acc[4][8][4];
#pragma unroll
    for (int i = 0; i < 4; i++)
#pragma unroll
        for (int j = 0; j < 8; j++)
#pragma unroll
            for (int r = 0; r < 4; r++) acc[i][j][r] = 0.f;

    // staging: r = tid>>1 (0..127), half h = tid&1 (16 cols)
    const int r = tid >> 1;
    const int h = tid & 1;
    const __half* pWf = Wf + (size_t)(n0 + r) * K + h * 16;
    const uint32_t stoA0 = (uint32_t)(r * PITCH + h * 16);
    const uint32_t stoA1 = (uint32_t)((128 + r) * PITCH + h * 16);
    const uint32_t stoW  = stoA0;

    const float* pA0f = Ain + (size_t)(m0 + r) * K + h * 16;
    const float* pA1f = Ain + (size_t)(m0 + 128 + r) * K + h * 16;
    float4 va0[4], va1[4];
    const __half* pAh0 = g_athi + (size_t)(m0 + r) * K + h * 16;
    const __half* pAl0 = g_atlo + (size_t)(m0 + r) * K + h * 16;
    const __half* pAh1 = g_athi + (size_t)(m0 + 128 + r) * K + h * 16;
    const __half* pAl1 = g_atlo + (size_t)(m0 + 128 + r) * K + h * 16;
    uint4 ra[8];
    uint4 rw[2];

    if (EPI == 1) {
#pragma unroll
        for (int i = 0; i < 4; i++) {
            va0[i] = *(const float4*)(pA0f + i * 4);
            va1[i] = *(const float4*)(pA1f + i * 4);
        }
    } else {
        ra[0] = *(const uint4*)(pAh0);     ra[1] = *(const uint4*)(pAh0 + 8);
        ra[2] = *(const uint4*)(pAl0);     ra[3] = *(const uint4*)(pAl0 + 8);
        ra[4] = *(const uint4*)(pAh1);     ra[5] = *(const uint4*)(pAh1 + 8);
        ra[6] = *(const uint4*)(pAl1);     ra[7] = *(const uint4*)(pAl1 + 8);
    }
    rw[0] = *(const uint4*)(pWf);
    rw[1] = *(const uint4*)(pWf + 8);

    for (int c = 0; c < 64; c++) {
        const uint32_t bufB = (uint32_t)((c & 1) * BUF_B);
        char* sb0 = sm_bf + bufB;
        if (EPI == 1) {
            stage_row_hl(va0, sb0 + (size_t)stoA0 * 2,
                         sb0 + A_ARR + (size_t)stoA0 * 2);
            stage_row_hl(va1, sb0 + (size_t)stoA1 * 2,
                         sb0 + A_ARR + (size_t)stoA1 * 2);
        } else {
            *(uint4*)(sb0 + (size_t)stoA0 * 2) = ra[0];
            *(uint4*)(sb0 + (size_t)stoA0 * 2 + 16) = ra[1];
            *(uint4*)(sb0 + A_ARR + (size_t)stoA0 * 2) = ra[2];
            *(uint4*)(sb0 + A_ARR + (size_t)stoA0 * 2 + 16) = ra[3];
            *(uint4*)(sb0 + (size_t)stoA1 * 2) = ra[4];
            *(uint4*)(sb0 + (size_t)stoA1 * 2 + 16) = ra[5];
            *(uint4*)(sb0 + A_ARR + (size_t)stoA1 * 2) = ra[6];
            *(uint4*)(sb0 + A_ARR + (size_t)stoA1 * 2 + 16) = ra[7];
        }
        *(uint4*)(sb0 + 2 * A_ARR + (size_t)stoW * 2) = rw[0];
        *(uint4*)(sb0 + 2 * A_ARR + (size_t)stoW * 2 + 16) = rw[1];

        if (c < 63) {
            const int o = (c + 1) * 32;
            if (EPI == 1) {
#pragma unroll
                for (int i = 0; i < 4; i++) {
                    va0[i] = *(const float4*)(pA0f + o + i * 4);
                    va1[i] = *(const float4*)(pA1f + o + i * 4);
                }
            } else {
                ra[0] = *(const uint4*)(pAh0 + o);
                ra[1] = *(const uint4*)(pAh0 + o + 8);
                ra[2] = *(const uint4*)(pAl0 + o);
                ra[3] = *(const uint4*)(pAl0 + o + 8);
                ra[4] = *(const uint4*)(pAh1 + o);
                ra[5] = *(const uint4*)(pAh1 + o + 8);
                ra[6] = *(const uint4*)(pAl1 + o);
                ra[7] = *(const uint4*)(pAl1 + o + 8);
            }
            rw[0] = *(const uint4*)(pWf + o);
            rw[1] = *(const uint4*)(pWf + o + 8);
        }
        __syncthreads();

        const uint32_t st = sbase + bufB;
#pragma unroll
        for (int ks = 0; ks < 2; ks++) {
            const uint32_t kb = (uint32_t)(ks * 32);
            uint32_t ah[4][4], al[4][4];
#pragma unroll
            for (int mi = 0; mi < 4; mi++) {
                const uint32_t off = aOff + (uint32_t)(mi * 16 * PITCH * 2) + kb;
                ldm_x4(ah[mi], st + off);
                ldm_x4(al[mi], st + A_ARR + off);
            }
#pragma unroll
            for (int njh = 0; njh < 2; njh++) {
                uint32_t bf[2][4];
#pragma unroll
                for (int pj = 0; pj < 2; pj++) {
                    const uint32_t off =
                        bOff + (uint32_t)((njh * 2 + pj) * 16 * PITCH * 2) + kb;
                    ldm_x4(bf[pj], st + 2 * A_ARR + off);
                }
#pragma unroll
                for (int mi = 0; mi < 4; mi++)
#pragma unroll
                    for (int njl = 0; njl < 4; njl++) {
                        float* a4 = acc[mi][njh * 4 + njl];
                        const uint32_t* bfp = &bf[njl >> 1][(njl & 1) * 2];
                        mma_f16(a4, ah[mi], bfp);
                        mma_f16(a4, al[mi], bfp);
                    }
            }
        }
    }

    // Epilogue
    const int t4 = lid >> 2;
    const int t2 = (lid & 3) << 1;
    if (EPI == 1) {
        const int seg = n0 >> 7;
        const int hh = (int)((unsigned)seg / 3u);
        const int which = seg - hh * 3;
        const float scl = (which == 0) ? 0.08838834764831845f : 1.0f;
        float* fpb = (which == 1) ? kout : vout;
#pragma unroll
        for (int mi = 0; mi < 4; mi++) {
            const int mrow = m0 + warpM * 64 + mi * 16 + t4;
            const int bb = mrow >> 11, ss = mrow & 2047;
            const size_t i0 = (((size_t)(bb * NHEAD + hh)) * SLEN + ss) * HS;
            const size_t i1 = i0 + 8 * HS;
#pragma unroll
            for (int nj = 0; nj < 8; nj++) {
                const int col = warpN * 64 + nj * 8 + t2;
                const float2 bv = *(const float2*)(bias + n0 + col);
                float x0 = acc[mi][nj][0] + bv.x, x1 = acc[mi][nj][1] + bv.y;
                float y0 = acc[mi][nj][2] + bv.x, y1 = acc[mi][nj][3] + bv.y;
                if (which == 0) {
                    x0 *= scl; x1 *= scl; y0 *= scl; y1 *= scl;
                    __half2 hx = __floats2half2_rn(x0, x1);
                    float2 hf = __half22float2(hx);
                    __half2 lx = __floats2half2_rn(x0 - hf.x, x1 - hf.y);
                    __half2 hy = __floats2half2_rn(y0, y1);
                    float2 hg = __half22float2(hy);
                    __half2 ly = __floats2half2_rn(y0 - hg.x, y1 - hg.y);
                    *(__half2*)(g_qhi + i0 + col) = hx;
                    *(__half2*)(g_qlo + i0 + col) = lx;
                    *(__half2*)(g_qhi + i1 + col) = hy;
                    *(__half2*)(g_qlo + i1 + col) = ly;
                } else {
                    *(float2*)(fpb + i0 + col) = make_float2(x0, x1);
                    *(float2*)(fpb + i1 + col) = make_float2(y0, y1);
                    __half* hf16 = (which == 1) ? g_kf : g_vf;
                    *(__half2*)(hf16 + i0 + col) = __floats2half2_rn(x0, x1);
                    *(__half2*)(hf16 + i1 + col) = __floats2half2_rn(y0, y1);
                }
            }
        }
    } else {
#pragma unroll
        for (int mi = 0; mi < 4; mi++) {
            const int mrow = m0 + warpM * 64 + mi * 16 + t4;
            float* d0 = C + (size_t)mrow * DM + n0;
            float* d1 = C + (size_t)(mrow + 8) * DM + n0;
#pragma unroll
            for (int nj = 0; nj < 8; nj++) {
                const int col = warpN * 64 + nj * 8 + t2;
                const float2 bv = *(const float2*)(bias + n0 + col);
                *(float2*)(d0 + col) =
                    make_float2(acc[mi][nj][0] + bv.x, acc[mi][nj][1] + bv.y);
                *(float2*)(d1 + col) =
                    make_float2(acc[mi][nj][2] + bv.x, acc[mi][nj][3] + bv.y);
            }
        }
    }
}

// ---------------------------------------------------------------------------
// Flash attention via mma.sync, causal. fp16: Q split hi/lo, K single,
// P single, V single — unchanged from R16.
// ---------------------------------------------------------------------------
#define QT 128
#define KT 64
#define Q_BYTES 32768
#define KV_ARR 16384
#define KV_BUF (2 * KV_ARR)
#define ATT_SMEM (2 * Q_BYTES + 2 * KV_BUF)  // 131072

__device__ __forceinline__ uint32_t swz(int row, int chunk) {
    return (uint32_t)(row * 256 + ((chunk ^ (row & 7)) << 4));
}

__global__ __launch_bounds__(256) void attn_mma_kernel()
{
    extern __shared__ __align__(16) char sm[];
    const uint32_t sb = smem_u32(sm);
    const int tid = threadIdx.x, wid = tid >> 5, lane = tid & 31;
    const int qb = blockIdx.x, bh = blockIdx.y;
    const int q0 = qb * QT;
    const int nkt = 2 * qb + 2;

    const size_t qoff = ((size_t)bh * SLEN + q0) * HS;
    const size_t kvoff = (size_t)bh * SLEN * HS;

    {
        const int half = tid >> 7;
        const __half* src = (half ? g_qlo : g_qhi) + qoff;
        char* base = sm + half * Q_BYTES;
        int rc = tid & 127;
#pragma unroll
        for (int t = 0; t < 16; t++, rc += 128) {
            const int row = rc >> 4, c = rc & 15;
            uint4 v = *(const uint4*)(src + row * HS + c * 8);
            *(uint4*)(base + swz(row, c)) = v;
        }
    }

    const int karr = tid >> 7;   // 0: K, 1: V
    const __half* ksrc = ((karr == 0) ? g_kf : g_vf) + kvoff;
    const uint32_t kdstArr = sb + 2 * Q_BYTES + (uint32_t)(karr * KV_ARR);

    auto kv_issue = [&](int kt, int bf) {
        const __half* s = ksrc + (size_t)kt * KT * HS;
        const uint32_t dbase = kdstArr + (uint32_t)(bf * KV_BUF);
        int rc = tid & 127;
#pragma unroll
        for (int t = 0; t < 8; t++, rc += 128) {
            const int row = rc >> 4, c = rc & 15;
            CP_ASYNC16(dbase + swz(row, c), s + row * HS + c * 8);
        }
    };

    kv_issue(0, 0);
    CP_COMMIT();

    float o[16][4];
#pragma unroll
    for (int t = 0; t < 16; t++)
#pragma unroll
        for (int r = 0; r < 4; r++) o[t][r] = 0.f;
    float m0r = -INFINITY, m1r = -INFINITY, l0r = 0.f, l1r = 0.f;

    const int aRow = wid * 16 + (lane & 7) + ((lane >> 3) & 1) * 8;
    const int aCh = lane >> 4;
    const int bRowK = (lane & 7) + (lane >> 4) * 8;
    const int bChK = (lane >> 3) & 1;
    const int vRow = (lane & 7) + ((lane >> 3) & 1) * 8;
    const int vCh = lane >> 4;

    for (int kt = 0; kt < nkt; kt++) {
        if (kt + 1 < nkt) {
            kv_issue(kt + 1, (kt + 1) & 1);
            CP_COMMIT();
            CP_WAIT1();
        } else {
            CP_WAIT0();
        }
        __syncthreads();

        const uint32_t kvb = sb + 2 * Q_BYTES + (uint32_t)((kt & 1) * KV_BUF);

        float s[8][4];
#pragma unroll
        for (int nj = 0; nj < 8; nj++)
#pragma unroll
            for (int r = 0; r < 4; r++) s[nj][r] = 0.f;

#pragma unroll
        for (int ks = 0; ks < 8; ks++) {
            uint32_t qh[4], ql[4];
            const uint32_t qa = sb + swz(aRow, 2 * ks + aCh);
            ldm_x4(qh, qa);
            ldm_x4(ql, qa + Q_BYTES);
#pragma unroll
            for (int njp = 0; njp < 4; njp++) {
                uint32_t kf[4];
                const uint32_t ka = kvb + swz(njp * 16 + bRowK, 2 * ks + bChK);
                ldm_x4(kf, ka);
                mma_f16(s[2 * njp], qh, kf);
                mma_f16(s[2 * njp], ql, kf);
                mma_f16(s[2 * njp + 1], qh, kf + 2);
                mma_f16(s[2 * njp + 1], ql, kf + 2);
            }
        }

        const int r0g = q0 + wid * 16 + (lane >> 2);
        if (kt >= 2 * qb) {
            const int cb = kt * KT + (lane & 3) * 2;
#pragma unroll
            for (int nj = 0; nj < 8; nj++) {
                const int c0 = cb + nj * 8;
                if (c0 > r0g)         s[nj][0] = -INFINITY;
                if (c0 + 1 > r0g)     s[nj][1] = -INFINITY;
                if (c0 > r0g + 8)     s[nj][2] = -INFINITY;
                if (c0 + 1 > r0g + 8) s[nj][3] = -INFINITY;
            }
        }

        float tm0 = -INFINITY, tm1 = -INFINITY;
#pragma unroll
        for (int nj = 0; nj < 8; nj++) {
            tm0 = fmaxf(tm0, fmaxf(s[nj][0], s[nj][1]));
            tm1 = fmaxf(tm1, fmaxf(s[nj][2], s[nj][3]));
        }
        tm0 = fmaxf(tm0, __shfl_xor_sync(0xffffffffu, tm0, 1));
        tm0 = fmaxf(tm0, __shfl_xor_sync(0xffffffffu, tm0, 2));
        tm1 = fmaxf(tm1, __shfl_xor_sync(0xffffffffu, tm1, 1));
        tm1 = fmaxf(tm1, __shfl_xor_sync(0xffffffffu, tm1, 2));
        const float mn0 = fmaxf(m0r, tm0), mn1 = fmaxf(m1r, tm1);
        const float a0 = __expf(m0r - mn0), a1 = __expf(m1r - mn1);
        m0r = mn0; m1r = mn1;

        float ls0 = 0.f, ls1 = 0.f;
        uint32_t pa[4][4];
#pragma unroll
        for (int nj = 0; nj < 8; nj++) {
            const float p0 = __expf(s[nj][0] - mn0);
            const float p1 = __expf(s[nj][1] - mn0);
            const float p2 = __expf(s[nj][2] - mn1);
            const float p3 = __expf(s[nj][3] - mn1);
            ls0 += p0 + p1;
            ls1 += p2 + p3;
            __half2 h01 = __floats2half2_rn(p0, p1);
            __half2 h23 = __floats2half2_rn(p2, p3);
            const int j = nj >> 1, e = (nj & 1) * 2;
            pa[j][e] = *(uint32_t*)&h01;
            pa[j][e + 1] = *(uint32_t*)&h23;
        }
        ls0 += __shfl_xor_sync(0xffffffffu, ls0, 1);
        ls0 += __shfl_xor_sync(0xffffffffu, ls0, 2);
        ls1 += __shfl_xor_sync(0xffffffffu, ls1, 1);
        ls1 += __shfl_xor_sync(0xffffffffu, ls1, 2);
        l0r = l0r * a0 + ls0;
        l1r = l1r * a1 + ls1;

#pragma unroll
        for (int t = 0; t < 16; t++) {
            o[t][0] *= a0; o[t][1] *= a0;
            o[t][2] *= a1; o[t][3] *= a1;
        }

#pragma unroll
        for (int j = 0; j < 4; j++) {
#pragma unroll
            for (int nd = 0; nd < 8; nd++) {
                uint32_t vf[4];
                const uint32_t va =
                    kvb + KV_ARR + swz(j * 16 + vRow, 2 * nd + vCh);
                ldm_x4_t(vf, va);
                mma_f16(o[2 * nd], pa[j], vf);
                mma_f16(o[2 * nd + 1], pa[j], vf + 2);
            }
        }
        __syncthreads();
    }

    // write attn_o as fp16 hi/lo (consumed by FF GEMM)
    const float inv0 = 1.f / l0r, inv1 = 1.f / l1r;
    const int b = bh >> 4, h = bh & 15;
    const int r0g = q0 + wid * 16 + (lane >> 2);
    const size_t base0 =
        ((size_t)(b * SLEN + r0g)) * DM + h * HS + (lane & 3) * 2;
    const size_t base1 = base0 + (size_t)8 * DM;
#pragma unroll
    for (int t = 0; t < 16; t++) {
        float v0 = o[t][0] * inv0, v1 = o[t][1] * inv0;
        float w0 = o[t][2] * inv1, w1 = o[t][3] * inv1;
        __half2 h0 = __floats2half2_rn(v0, v1);
        float2 f0 = __half22float2(h0);
        __half2 l0 = __floats2half2_rn(v0 - f0.x, v1 - f0.y);
        __half2 h1 = __floats2half2_rn(w0, w1);
        float2 f1 = __half22float2(h1);
        __half2 l1 = __floats2half2_rn(w0 - f1.x, w1 - f1.y);
        *(__half2*)(g_athi + base0 + t * 8) = h0;
        *(__half2*)(g_atlo + base0 + t * 8) = l0;
        *(__half2*)(g_athi + base1 + t * 8) = h1;
        *(__half2*)(g_atlo + base1 + t * 8) = l1;
    }
}

// ---------------------------------------------------------------------------
extern "C" void kernel_launch(void* const* d_in, const int* in_sizes, int n_in,
                              void* d_out, int out_size)
{
    const float* x      = (const float*)d_in[0];
    const float* w_proj = (const float*)d_in[1];
    const float* b_proj = (const float*)d_in[2];
    const float* w_ff   = (const float*)d_in[3];
    const float* b_ff   = (const float*)d_in[4];

    float* out = (float*)d_out;
    float* ff   = out;
    float* kout = out + (size_t)BATCH * SLEN * DM;
    float* vout = kout + (size_t)BATCH * NHEAD * SLEN * HS;

    cudaFuncSetAttribute(attn_mma_kernel,
                         cudaFuncAttributeMaxDynamicSharedMemorySize, ATT_SMEM);
    cudaFuncSetAttribute(gemm_mma_kernel<1>,
                         cudaFuncAttributeMaxDynamicSharedMemorySize, GEMM_SMEM);
    cudaFuncSetAttribute(gemm_mma_kernel<2>,
                         cudaFuncAttributeMaxDynamicSharedMemorySize, GEMM_SMEM);

    __half *wpf, *wff;
    cudaGetSymbolAddress((void**)&wpf, g_wpf);
    cudaGetSymbolAddress((void**)&wff, g_wff);

    // 0) pre-convert weights fp32 -> fp16 (bit-identical rounding)
    conv_kernel<<<2048, 256>>>((const float4*)w_proj, (uint2*)wpf,
                               (EPROJ * DM) / 4);
    conv_kernel<<<1024, 256>>>((const float4*)w_ff, (uint2*)wff,
                               (DM * DM) / 4);

    // 1) QKV projection: q(scaled) fp16 hi/lo, k/v fp32 d_out + fp16 scratch
    gemm_mma_kernel<1><<<dim3(EPROJ / 128, (BATCH * SLEN) / 256), 256, GEMM_SMEM>>>(
        x, wpf, b_proj, (float*)nullptr, kout, vout);

    // 2) Causal flash attention (fp16 mma.sync) -> g_athi/g_atlo
    attn_mma_kernel<<<dim3(SLEN / QT, BATCH * NHEAD), 256, ATT_SMEM>>>();

    // 3) FF projection (A pre-split fp16) -> ff output
    gemm_mma_kernel<2><<<dim3(DM / 128, (BATCH * SLEN) / 256), 256, GEMM_SMEM>>>(
        (const float*)nullptr, wff, b_ff, ff, (float*)nullptr, (float*)nullptr);
}